// round 1
// baseline (speedup 1.0000x reference)
#include <cuda_runtime.h>

// ---------------------------------------------------------------------------
// effConvKAN3D: fused unfold3d(k=3,pad=1) + KANLinear(216 -> 16) over (1,8,32^3)
// out[o, z, y, x] = sum_f silu(v_f)*Wb[o,f] + sum_c B_c(v_f)*Ws[o,f,c]*scaler[o,f]
// Cubic B-spline on uniform grid: exactly 4 nonzero bases per value,
// closed-form cubic polynomials (no recursion).
// ---------------------------------------------------------------------------

#define IN_CH   8
#define OUT_CH  16
#define DIM     32
#define NF      216      // 8 * 27 input features
#define NC      8        // GRID_SIZE + SPLINE_ORDER
#define PADC    20       // padded o-stride (floats) per (f,c) row: 80B -> conflict-free
#define TW      8
#define TH      8
#define TD      4
#define HW      (TW + 2)
#define HH      (TH + 2)
#define HD      (TD + 2)
#define XT_ELEMS  (IN_CH * HD * HH * HW)   // 8*6*10*10 = 4800
#define WSP_ELEMS (NF * NC * PADC)          // 34560
#define WB_ELEMS  (NF * OUT_CH)             // 3456
#define SMEM_FLOATS (WSP_ELEMS + WB_ELEMS + XT_ELEMS)  // 42816 -> 171264 B

__device__ float g_Wsp[WSP_ELEMS];   // [f][c][o(pad 20)] = spline_w[o][f][c] * scaler[o][f]
__device__ float g_Wb[WB_ELEMS];     // [f][o]            = base_w[o][f]

__global__ void prep_kernel(const float* __restrict__ bw,
                            const float* __restrict__ sw,
                            const float* __restrict__ sc) {
    int t = blockIdx.x * blockDim.x + threadIdx.x;
    if (t < WB_ELEMS) {
        int o = t / NF, f = t - o * NF;
        g_Wb[f * OUT_CH + o] = bw[t];
    }
    if (t < NF * NC * OUT_CH) {
        int o = t / (NF * NC);
        int r = t - o * NF * NC;
        int f = r >> 3, c = r & 7;
        g_Wsp[(f * NC + c) * PADC + o] = sw[t] * sc[o * NF + f];
    }
}

__global__ __launch_bounds__(256, 1)
void kan_kernel(const float* __restrict__ x, float* __restrict__ out) {
    extern __shared__ float smem[];
    float* sWsp = smem;                       // 34560 floats
    float* sWb  = smem + WSP_ELEMS;           // 3456 floats
    float* sX   = smem + WSP_ELEMS + WB_ELEMS;// 4800 floats

    const int tid = threadIdx.x;

    // ---- cooperative copy of packed weights (float4) ----
    {
        const float4* src = reinterpret_cast<const float4*>(g_Wsp);
        float4*       dst = reinterpret_cast<float4*>(sWsp);
        #pragma unroll 4
        for (int i = tid; i < WSP_ELEMS / 4; i += 256) dst[i] = src[i];
        const float4* srcb = reinterpret_cast<const float4*>(g_Wb);
        float4*       dstb = reinterpret_cast<float4*>(sWb);
        for (int i = tid; i < WB_ELEMS / 4; i += 256) dstb[i] = srcb[i];
    }

    // ---- x halo tile (zero padded) ----
    const int xb = blockIdx.x * TW;
    const int yb = blockIdx.y * TH;
    const int zb = blockIdx.z * TD;
    for (int idx = tid; idx < XT_ELEMS; idx += 256) {
        int c  = idx / (HD * HH * HW);
        int r  = idx - c * (HD * HH * HW);
        int zz = r / (HH * HW);
        int r2 = r - zz * (HH * HW);
        int yy = r2 / HW;
        int xx = r2 - yy * HW;
        int gz = zb + zz - 1, gy = yb + yy - 1, gx = xb + xx - 1;
        float v = 0.0f;
        if ((unsigned)gz < (unsigned)DIM && (unsigned)gy < (unsigned)DIM &&
            (unsigned)gx < (unsigned)DIM)
            v = x[((c * DIM + gz) * DIM + gy) * DIM + gx];
        sX[idx] = v;
    }
    __syncthreads();

    const int lx = tid & 7;
    const int ly = (tid >> 3) & 7;
    const int lz = tid >> 6;

    float acc[16];
    #pragma unroll
    for (int o = 0; o < 16; o++) acc[o] = 0.0f;

    const float4* sWsp4 = reinterpret_cast<const float4*>(sWsp);
    const float4* sWb4  = reinterpret_cast<const float4*>(sWb);

    int f = 0;
    #pragma unroll 1
    for (int c = 0; c < IN_CH; c++) {
        #pragma unroll 1
        for (int dz = 0; dz < 3; dz++) {
            #pragma unroll 1
            for (int dy = 0; dy < 3; dy++) {
                const float* xrow = &sX[((c * HD + lz + dz) * HH + ly + dy) * HW + lx];
                #pragma unroll
                for (int dx = 0; dx < 3; dx++, f++) {
                    float v = xrow[dx];

                    // silu(v) = v / (1 + exp(-v))
                    float e = __expf(-v);
                    float s = __fdividef(v, 1.0f + e);

                    // cubic B-spline: interval + local coord on uniform grid
                    // grid spans [-2.2, 2.2], h = 0.4, 11 intervals (j = 0..10)
                    float t  = (v + 2.2f) * 2.5f;
                    float jf = floorf(t);
                    float u  = t - jf;
                    int   j  = (int)jf;

                    float u2 = u * u, u3 = u2 * u;
                    float om = 1.0f - u;
                    float b0 = om * om * om * (1.0f / 6.0f);                       // idx j-3
                    float b1 = fmaf(3.0f, u3, fmaf(-6.0f, u2, 4.0f)) * (1.0f/6.0f); // idx j-2
                    float b2 = fmaf(-3.0f, u3, fmaf(3.0f, u2, fmaf(3.0f, u, 1.0f)))
                               * (1.0f / 6.0f);                                    // idx j-1
                    float b3 = u3 * (1.0f / 6.0f);                                 // idx j

                    if ((unsigned)j > 10u) { b0 = b1 = b2 = b3 = 0.0f; j = 3; }
                    int i0 = j - 3, i1 = j - 2, i2 = j - 1, i3 = j;
                    if (i0 < 0) b0 = 0.0f;
                    if (i1 < 0) b1 = 0.0f;
                    if (i2 < 0) b2 = 0.0f;
                    if (i1 > 7) b1 = 0.0f;
                    if (i2 > 7) b2 = 0.0f;
                    if (i3 > 7) b3 = 0.0f;
                    i0 = max(i0, 0);
                    i1 = min(max(i1, 0), 7);
                    i2 = min(max(i2, 0), 7);
                    i3 = min(i3, 7);

                    const int fb = f * NC;
                    const float4* W0 = sWsp4 + (fb + i0) * (PADC / 4);
                    const float4* W1 = sWsp4 + (fb + i1) * (PADC / 4);
                    const float4* W2 = sWsp4 + (fb + i2) * (PADC / 4);
                    const float4* W3 = sWsp4 + (fb + i3) * (PADC / 4);
                    const float4* WB = sWb4 + f * 4;

                    #pragma unroll
                    for (int q = 0; q < 4; q++) {
                        float4 wb = WB[q];
                        float4 w0 = W0[q];
                        float4 w1 = W1[q];
                        float4 w2 = W2[q];
                        float4 w3 = W3[q];
                        float a0 = acc[4*q+0], a1 = acc[4*q+1];
                        float a2 = acc[4*q+2], a3 = acc[4*q+3];
                        a0 = fmaf(s, wb.x, a0); a0 = fmaf(b0, w0.x, a0);
                        a0 = fmaf(b1, w1.x, a0); a0 = fmaf(b2, w2.x, a0);
                        a0 = fmaf(b3, w3.x, a0);
                        a1 = fmaf(s, wb.y, a1); a1 = fmaf(b0, w0.y, a1);
                        a1 = fmaf(b1, w1.y, a1); a1 = fmaf(b2, w2.y, a1);
                        a1 = fmaf(b3, w3.y, a1);
                        a2 = fmaf(s, wb.z, a2); a2 = fmaf(b0, w0.z, a2);
                        a2 = fmaf(b1, w1.z, a2); a2 = fmaf(b2, w2.z, a2);
                        a2 = fmaf(b3, w3.z, a2);
                        a3 = fmaf(s, wb.w, a3); a3 = fmaf(b0, w0.w, a3);
                        a3 = fmaf(b1, w1.w, a3); a3 = fmaf(b2, w2.w, a3);
                        a3 = fmaf(b3, w3.w, a3);
                        acc[4*q+0] = a0; acc[4*q+1] = a1;
                        acc[4*q+2] = a2; acc[4*q+3] = a3;
                    }
                }
            }
        }
    }

    // ---- write out: out[o][z][y][x] ----
    const int gz = zb + lz, gy = yb + ly, gx = xb + lx;
    const int sp = (gz * DIM + gy) * DIM + gx;
    #pragma unroll
    for (int o = 0; o < 16; o++)
        out[o * (DIM * DIM * DIM) + sp] = acc[o];
}

extern "C" void kernel_launch(void* const* d_in, const int* in_sizes, int n_in,
                              void* d_out, int out_size) {
    const float* x  = (const float*)d_in[0];
    const float* bw = (const float*)d_in[1];
    const float* sw = (const float*)d_in[2];
    const float* sc = (const float*)d_in[3];

    prep_kernel<<<(NF * NC * OUT_CH + 255) / 256, 256>>>(bw, sw, sc);

    size_t smem = SMEM_FLOATS * sizeof(float);
    cudaFuncSetAttribute(kan_kernel, cudaFuncAttributeMaxDynamicSharedMemorySize,
                         (int)smem);
    kan_kernel<<<dim3(DIM / TW, DIM / TH, DIM / TD), 256, smem>>>(x, (float*)d_out);
}

// round 4
// speedup vs baseline: 1.3765x; 1.3765x over previous
#include <cuda_runtime.h>
#include <cuda_fp16.h>
#include <cstdint>

// ---------------------------------------------------------------------------
// effConvKAN3D as an f16 HMMA (mma.sync.m16n8k16) GEMM:
//   out[M=32768,16] = A[M,K] * B[16,K]^T, fp32 accumulate.
// K layout: [0,216) silu(v_f); [216,224) zero; [224,1952) basis_c(v_f),
//           f=(k-224)/8, c=(k-224)%8 (4 of 8 nonzero, closed-form cubic).
// ---------------------------------------------------------------------------

#define NF      216
#define KP      1960           // padded B row stride (halves); 3920 B -> conflict-free LDS
#define NSIL    14             // silu k-chunks (k 0..223)
#define NSPL    108            // spline k-chunks (k 224..1951)
#define OSTRIDE 32768

#define SB_BYTES  (16 * KP * 2)          // 62720
#define SA_OFF    SB_BYTES
#define SA_STRIDE 768                    // per-warp A tile: 16 rows x 48 B
#define ST_OFF    (SA_OFF + 8 * SA_STRIDE)   // 68864
#define SMEM_BYTES (ST_OFF + NF * 8)         // 70592

__device__ __align__(16) __half g_B[16 * KP];
__device__ __align__(16) int2   g_tab[NF];

// ---- prep: pack B (f16) + gather table -----------------------------------
__global__ void prep_kernel(const float* __restrict__ bw,
                            const float* __restrict__ sw,
                            const float* __restrict__ sc) {
    int t = blockIdx.x * 256 + threadIdx.x;
    if (t < NF) {
        int c = t / 27, r = t - c * 27;
        int dz = r / 9, r2 = r - dz * 9;
        int dy = r2 / 3, dx = r2 - dy * 3;
        int off = c * 32768 + (dz - 1) * 1024 + (dy - 1) * 32 + (dx - 1);
        g_tab[t] = make_int2(off, dz | (dy << 8) | (dx << 16));
    }
    if (t < 16 * KP) {
        int o = t / KP, k = t - o * KP;
        float val = 0.0f;
        if (k < NF) {
            val = bw[o * NF + k];
        } else if (k >= 224 && k < 1952) {
            int f = (k - 224) >> 3, c = (k - 224) & 7;
            val = sw[(o * NF + f) * 8 + c] * sc[o * NF + f];
        }
        g_B[t] = __float2half_rn(val);
    }
}

// ---- gather one unfold feature value --------------------------------------
__device__ __forceinline__ float feat(const float* __restrict__ x,
                                      const int2* __restrict__ tab,
                                      int pos, int pz, int py, int px, int f) {
    int2 tv = tab[f];
    int dz = (tv.y & 0xFF) - 1;
    int dy = ((tv.y >> 8) & 0xFF) - 1;
    int dx = ((tv.y >> 16) & 0xFF) - 1;
    bool ok = ((unsigned)(pz + dz) < 32u) && ((unsigned)(py + dy) < 32u) &&
              ((unsigned)(px + dx) < 32u);
    return ok ? __ldg(x + pos + tv.x) : 0.0f;
}

#define MMA_STEP(KC) do {                                                     \
    uint32_t a0 = *(const uint32_t*)(aR0);                                    \
    uint32_t a1 = *(const uint32_t*)(aR1);                                    \
    uint32_t a2 = *(const uint32_t*)(aR0 + 16);                               \
    uint32_t a3 = *(const uint32_t*)(aR1 + 16);                               \
    uint32_t b0 = *(const uint32_t*)(bR0 + (KC) * 32);                        \
    uint32_t b1 = *(const uint32_t*)(bR0 + (KC) * 32 + 16);                   \
    uint32_t b2 = *(const uint32_t*)(bR1 + (KC) * 32);                        \
    uint32_t b3 = *(const uint32_t*)(bR1 + (KC) * 32 + 16);                   \
    asm volatile("mma.sync.aligned.m16n8k16.row.col.f32.f16.f16.f32 "         \
        "{%0,%1,%2,%3}, {%4,%5,%6,%7}, {%8,%9}, {%0,%1,%2,%3};"               \
        : "+f"(d00), "+f"(d01), "+f"(d02), "+f"(d03)                          \
        : "r"(a0), "r"(a1), "r"(a2), "r"(a3), "r"(b0), "r"(b1));              \
    asm volatile("mma.sync.aligned.m16n8k16.row.col.f32.f16.f16.f32 "         \
        "{%0,%1,%2,%3}, {%4,%5,%6,%7}, {%8,%9}, {%0,%1,%2,%3};"               \
        : "+f"(d10), "+f"(d11), "+f"(d12), "+f"(d13)                          \
        : "r"(a0), "r"(a1), "r"(a2), "r"(a3), "r"(b2), "r"(b3));              \
} while (0)

__global__ __launch_bounds__(256, 2)
void kan_kernel(const float* __restrict__ x, float* __restrict__ out) {
    extern __shared__ char smem[];
    const int tid = threadIdx.x;

    // copy B tile + gather table into SMEM
    for (int i = tid; i < SB_BYTES / 16; i += 256)
        ((uint4*)smem)[i] = ((const uint4*)g_B)[i];
    for (int i = tid; i < (NF * 8) / 16; i += 256)
        ((uint4*)(smem + ST_OFF))[i] = ((const uint4*)g_tab)[i];
    __syncthreads();

    const int wid = tid >> 5, lane = tid & 31;
    const int r = lane & 15, s = lane >> 4;         // producer role
    const int posb = blockIdx.x * 128 + wid * 16;
    const int pos = posb + r;
    const int pz = pos >> 10, py = (pos >> 5) & 31, px = pos & 31;
    const int2* sTab = (const int2*)(smem + ST_OFF);
    char* sAw = smem + SA_OFF + wid * SA_STRIDE;
    uint4* sts = (uint4*)(sAw + r * 48 + s * 16);

    const int g = lane >> 2, t4 = lane & 3;         // mma fragment role
    const char* aR0 = sAw + g * 48 + t4 * 4;        // A row g,  cols 2t..
    const char* aR1 = sAw + (g + 8) * 48 + t4 * 4;  // A row g+8
    const char* bR0 = smem + g * (KP * 2) + t4 * 4;       // B row o=g
    const char* bR1 = smem + (g + 8) * (KP * 2) + t4 * 4; // B row o=g+8

    float d00 = 0, d01 = 0, d02 = 0, d03 = 0;
    float d10 = 0, d11 = 0, d12 = 0, d13 = 0;

    // ---- silu chunks (k-chunks 0..13) ----
    #pragma unroll 1
    for (int kc = 0; kc < NSIL; kc++) {
        uint32_t w[4];
        #pragma unroll
        for (int q = 0; q < 4; q++) {
            int f0 = kc * 16 + s * 8 + 2 * q;
            float v0 = (f0 < NF)     ? feat(x, sTab, pos, pz, py, px, f0)     : 0.0f;
            float v1 = (f0 + 1 < NF) ? feat(x, sTab, pos, pz, py, px, f0 + 1) : 0.0f;
            float s0 = __fdividef(v0, 1.0f + __expf(-v0));
            float s1 = __fdividef(v1, 1.0f + __expf(-v1));
            __half2 h = __floats2half2_rn(s0, s1);
            w[q] = *(uint32_t*)&h;
        }
        __syncwarp();
        *sts = make_uint4(w[0], w[1], w[2], w[3]);
        __syncwarp();
        MMA_STEP(kc);
    }

    // ---- spline chunks (k-chunks 14..121): 2 features per chunk ----
    #pragma unroll 1
    for (int kc2 = 0; kc2 < NSPL; kc2++) {
        int f = 2 * kc2 + s;                       // < 216 always
        float v = feat(x, sTab, pos, pz, py, px, f);

        // uniform cubic B-spline on grid [-2.2, 2.2], h = 0.4, intervals j=0..10
        float tt = fmaf(v, 2.5f, 5.5f);
        float jf = floorf(tt);
        float u = tt - jf;
        int j = (int)jf;
        float u2 = u * u, u3 = u2 * u, om = 1.0f - u;
        float b0 = om * om * om * (1.0f / 6.0f);
        float b1 = fmaf(3.0f, u3, fmaf(-6.0f, u2, 4.0f)) * (1.0f / 6.0f);
        float b2 = fmaf(-3.0f, u3, fmaf(3.0f, u2, fmaf(3.0f, u, 1.0f))) * (1.0f / 6.0f);
        float b3 = u3 * (1.0f / 6.0f);

        __half2 hlo = __floats2half2_rn(b0, b1);
        __half2 hhi = __floats2half2_rn(b2, b3);
        uint32_t lo = *(uint32_t*)&hlo, hi = *(uint32_t*)&hhi;
        if ((unsigned)j > 10u) { lo = 0u; hi = 0u; j = 3; }
        uint64_t B64 = (uint64_t)lo | ((uint64_t)hi << 32);
        int t16 = j - 3;                           // half-index of b0 within c=0..7

        uint32_t w[4];
        #pragma unroll
        for (int i = 0; i < 4; i++) {
            int d = 2 * i - t16;
            int shc = ((unsigned)d <= 3u) ? d : 0;
            uint32_t a = (uint32_t)(B64 >> (shc * 16));
            w[i] = ((unsigned)d <= 3u) ? a : ((d == -1) ? (lo << 16) : 0u);
        }
        __syncwarp();
        *sts = make_uint4(w[0], w[1], w[2], w[3]);
        __syncwarp();
        MMA_STEP(NSIL + kc2);
    }

    // ---- epilogue: d frag (rows g,g+8; cols 2t,2t+1 per n8 tile) ----
    const int pr0 = posb + g, pr1 = pr0 + 8;
    out[(2 * t4 + 0) * OSTRIDE + pr0] = d00;
    out[(2 * t4 + 1) * OSTRIDE + pr0] = d01;
    out[(2 * t4 + 0) * OSTRIDE + pr1] = d02;
    out[(2 * t4 + 1) * OSTRIDE + pr1] = d03;
    out[(2 * t4 + 8) * OSTRIDE + pr0] = d10;
    out[(2 * t4 + 9) * OSTRIDE + pr0] = d11;
    out[(2 * t4 + 8) * OSTRIDE + pr1] = d12;
    out[(2 * t4 + 9) * OSTRIDE + pr1] = d13;
}

extern "C" void kernel_launch(void* const* d_in, const int* in_sizes, int n_in,
                              void* d_out, int out_size) {
    const float* x  = (const float*)d_in[0];
    const float* bw = (const float*)d_in[1];
    const float* sw = (const float*)d_in[2];
    const float* sc = (const float*)d_in[3];

    prep_kernel<<<(16 * KP + 255) / 256, 256>>>(bw, sw, sc);

    cudaFuncSetAttribute(kan_kernel, cudaFuncAttributeMaxDynamicSharedMemorySize,
                         SMEM_BYTES);
    kan_kernel<<<256, 256, SMEM_BYTES>>>(x, (float*)d_out);
}

// round 5
// speedup vs baseline: 1.8374x; 1.3348x over previous
#include <cuda_runtime.h>
#include <cuda_fp16.h>
#include <cstdint>

// ---------------------------------------------------------------------------
// effConvKAN3D as f16 HMMA GEMM, grouped K layout:
//   14 groups of 16 features; per group: 8 spline chunks (2 feat x 8 basis
//   cols) + 1 silu chunk (16 silu cols). 126 chunks, K=2016.
// x gathered once per (pos,feature) from a CTA smem halo tile; silu values
// stashed during the spline pass and consumed by the group's silu chunk.
// ---------------------------------------------------------------------------

#define NF      216
#define NGRP    14
#define KP      2024            // B row stride (halves): 4048 B, conflict-free
#define OSTRIDE 32768

#define B_BYTES    (16 * KP * 2)              // 64768
#define TILE_OFF   B_BYTES
#define TILE_ELEMS (8 * 3 * 6 * 34)           // 4896 floats
#define AB_OFF     (TILE_OFF + TILE_ELEMS * 4)  // 84352
#define WARP_BYTES 2304                       // [A0 768][A1 768][stage 768]
#define OFFS_OFF   (AB_OFF + 8 * WARP_BYTES)  // 102784
#define SMEM_BYTES (OFFS_OFF + 224 * 4)       // 103680

__device__ __align__(16) __half   g_B[16 * KP];
__device__ __align__(16) uint32_t g_offs[224];

// ---- prep: grouped B layout + tile-offset table ---------------------------
__global__ void prep_kernel(const float* __restrict__ bw,
                            const float* __restrict__ sw,
                            const float* __restrict__ sc) {
    int t = blockIdx.x * 256 + threadIdx.x;
    if (t < 224) {
        uint32_t off = 0;
        if (t < NF) {
            int c = t / 27, r = t - c * 27;
            int dz = r / 9,  r2 = r - dz * 9;
            int dy = r2 / 3, dx = r2 - dy * 3;
            off = (uint32_t)((((c * 3 + dz) * 6 + dy) * 34 + dx) * 4);
        }
        g_offs[t] = off;
    }
    if (t < 16 * KP) {
        int o = t / KP, k = t - o * KP;
        float val = 0.0f;
        if (k < NGRP * 144) {                 // 2016 real K columns
            int g = k / 144, rem = k - g * 144;
            int w = rem >> 4, col = rem & 15;
            if (w < 8) {                       // spline chunk
                int f = 16 * g + 2 * w + (col >> 3), c = col & 7;
                if (f < NF) val = sw[(o * NF + f) * 8 + c] * sc[o * NF + f];
            } else {                           // silu chunk
                int f = 16 * g + col;
                if (f < NF) val = bw[o * NF + f];
            }
        }
        g_B[t] = __float2half_rn(val);
    }
}

#define MMA2(A0, A1, A2, A3, B0, B1, B2, B3) do {                             \
    asm volatile("mma.sync.aligned.m16n8k16.row.col.f32.f16.f16.f32 "         \
        "{%0,%1,%2,%3}, {%4,%5,%6,%7}, {%8,%9}, {%0,%1,%2,%3};"               \
        : "+f"(d00), "+f"(d01), "+f"(d02), "+f"(d03)                          \
        : "r"(A0), "r"(A1), "r"(A2), "r"(A3), "r"(B0), "r"(B1));              \
    asm volatile("mma.sync.aligned.m16n8k16.row.col.f32.f16.f16.f32 "         \
        "{%0,%1,%2,%3}, {%4,%5,%6,%7}, {%8,%9}, {%0,%1,%2,%3};"               \
        : "+f"(d10), "+f"(d11), "+f"(d12), "+f"(d13)                          \
        : "r"(A0), "r"(A1), "r"(A2), "r"(A3), "r"(B2), "r"(B3));              \
} while (0)

__global__ __launch_bounds__(256, 2)
void kan_kernel(const float* __restrict__ x, float* __restrict__ out) {
    extern __shared__ char smem[];
    const int tid = threadIdx.x;
    const int bid = blockIdx.x;

    // B tile copy
    for (int i = tid; i < B_BYTES / 16; i += 256)
        ((uint4*)smem)[i] = ((const uint4*)g_B)[i];
    if (tid < 224)
        ((uint32_t*)(smem + OFFS_OFF))[tid] = g_offs[tid];

    // x halo tile: [c 8][zz 3][yy 6][xx 34], zero padded
    const int z0 = bid >> 3, y0 = (bid & 7) * 4;
    float* tile = (float*)(smem + TILE_OFF);
    for (int i = tid; i < TILE_ELEMS; i += 256) {
        int c  = i / 612;            // 3*6*34
        int r1 = i - c * 612;
        int zz = r1 / 204;           // 6*34
        int r2 = r1 - zz * 204;
        int yy = r2 / 34;
        int xx = r2 - yy * 34;
        int gz = z0 - 1 + zz, gy = y0 - 1 + yy, gx = xx - 1;
        float v = 0.0f;
        if (((unsigned)gz < 32u) & ((unsigned)gy < 32u) & ((unsigned)gx < 32u))
            v = __ldg(x + ((c * 32 + gz) * 32 + gy) * 32 + gx);
        tile[i] = v;
    }
    __syncthreads();

    const int wid = tid >> 5, lane = tid & 31;
    const int r = lane & 15, s = lane >> 4;         // producer role
    const int yl = wid >> 1;
    const int xw = (wid & 1) * 16 + r;
    const uint32_t laneBase = (uint32_t)((yl * 34 + xw) * 4);
    const uint32_t* sOffs = (const uint32_t*)(smem + OFFS_OFF);
    const char* tileB = (const char*)tile;
    char* warpA = smem + AB_OFF + wid * WARP_BYTES;
    char* stage = warpA + 1536;

    const int g8 = lane >> 2, t4 = lane & 3;        // mma fragment role
    const int aO0 = g8 * 48 + t4 * 4;
    const int aO1 = (g8 + 8) * 48 + t4 * 4;
    const char* bBase = smem + g8 * (KP * 2) + t4 * 4;

    float d00 = 0, d01 = 0, d02 = 0, d03 = 0;
    float d10 = 0, d11 = 0, d12 = 0, d13 = 0;

    #pragma unroll 1
    for (int g = 0; g < NGRP; g++) {
        #pragma unroll
        for (int w = 0; w < 8; w++) {
            const int kc = 9 * g + w;
            const int f = 16 * g + 2 * w + s;
            const bool valid = (f < NF);
            uint32_t off = sOffs[f];
            float v = *(const float*)(tileB + off + laneBase);

            // silu stash (f16) for the group's silu chunk
            float sv = __fdividef(v, 1.0f + __expf(-v));
            *(__half*)(stage + r * 48 + (2 * w + s) * 2) =
                __float2half_rn(valid ? sv : 0.0f);

            // uniform cubic B-spline, grid [-2.2,2.2], h=0.4, j=0..10
            float tt = fmaf(v, 2.5f, 5.5f);
            float jf = floorf(tt);
            float u = tt - jf;
            int j = (int)jf;
            float u2 = u * u, u3 = u2 * u, om = 1.0f - u;
            float b0 = om * om * om * (1.0f / 6.0f);
            float b1 = fmaf(3.0f, u3, fmaf(-6.0f, u2, 4.0f)) * (1.0f / 6.0f);
            float b2 = fmaf(-3.0f, u3, fmaf(3.0f, u2, fmaf(3.0f, u, 1.0f)))
                       * (1.0f / 6.0f);
            float b3 = u3 * (1.0f / 6.0f);

            __half2 hlo = __floats2half2_rn(b0, b1);
            __half2 hhi = __floats2half2_rn(b2, b3);
            uint32_t lo = *(uint32_t*)&hlo, hi = *(uint32_t*)&hhi;
            if (((unsigned)j > 10u) | (!valid)) { lo = 0u; hi = 0u; j = 3; }
            uint64_t B64 = (uint64_t)lo | ((uint64_t)hi << 32);
            int t16 = j - 3;

            uint32_t wv[4];
            #pragma unroll
            for (int i4 = 0; i4 < 4; i4++) {
                int d = 2 * i4 - t16;
                int shc = ((unsigned)d <= 3u) ? d : 0;
                uint32_t a = (uint32_t)(B64 >> (shc * 16));
                wv[i4] = ((unsigned)d <= 3u) ? a : ((d == -1) ? (lo << 16) : 0u);
            }

            char* Ab = warpA + (kc & 1) * 768;
            *(uint4*)(Ab + r * 48 + s * 16) =
                make_uint4(wv[0], wv[1], wv[2], wv[3]);
            __syncwarp();

            uint32_t a0 = *(const uint32_t*)(Ab + aO0);
            uint32_t a1 = *(const uint32_t*)(Ab + aO1);
            uint32_t a2 = *(const uint32_t*)(Ab + aO0 + 16);
            uint32_t a3 = *(const uint32_t*)(Ab + aO1 + 16);
            const char* bp = bBase + kc * 32;
            uint32_t bb0 = *(const uint32_t*)(bp);
            uint32_t bb1 = *(const uint32_t*)(bp + 16);
            uint32_t bb2 = *(const uint32_t*)(bp + 8 * KP * 2);
            uint32_t bb3 = *(const uint32_t*)(bp + 8 * KP * 2 + 16);
            MMA2(a0, a1, a2, a3, bb0, bb1, bb2, bb3);
        }
        // silu chunk for this group: A straight from the stage buffer
        {
            const int kc = 9 * g + 8;
            uint32_t a0 = *(const uint32_t*)(stage + aO0);
            uint32_t a1 = *(const uint32_t*)(stage + aO1);
            uint32_t a2 = *(const uint32_t*)(stage + aO0 + 16);
            uint32_t a3 = *(const uint32_t*)(stage + aO1 + 16);
            const char* bp = bBase + kc * 32;
            uint32_t bb0 = *(const uint32_t*)(bp);
            uint32_t bb1 = *(const uint32_t*)(bp + 16);
            uint32_t bb2 = *(const uint32_t*)(bp + 8 * KP * 2);
            uint32_t bb3 = *(const uint32_t*)(bp + 8 * KP * 2 + 16);
            MMA2(a0, a1, a2, a3, bb0, bb1, bb2, bb3);
            __syncwarp();   // protect stage WAR vs next group's stashes
        }
    }

    // epilogue: d frag rows g8,g8+8; cols 2t4,2t4+1 (+8 for second MMA)
    const int posb = bid * 128 + wid * 16;
    const int pr0 = posb + g8, pr1 = pr0 + 8;
    out[(2 * t4 + 0) * OSTRIDE + pr0] = d00;
    out[(2 * t4 + 1) * OSTRIDE + pr0] = d01;
    out[(2 * t4 + 0) * OSTRIDE + pr1] = d02;
    out[(2 * t4 + 1) * OSTRIDE + pr1] = d03;
    out[(2 * t4 + 8) * OSTRIDE + pr0] = d10;
    out[(2 * t4 + 9) * OSTRIDE + pr0] = d11;
    out[(2 * t4 + 8) * OSTRIDE + pr1] = d12;
    out[(2 * t4 + 9) * OSTRIDE + pr1] = d13;
}

extern "C" void kernel_launch(void* const* d_in, const int* in_sizes, int n_in,
                              void* d_out, int out_size) {
    const float* x  = (const float*)d_in[0];
    const float* bw = (const float*)d_in[1];
    const float* sw = (const float*)d_in[2];
    const float* sc = (const float*)d_in[3];

    prep_kernel<<<(16 * KP + 255) / 256, 256>>>(bw, sw, sc);

    cudaFuncSetAttribute(kan_kernel, cudaFuncAttributeMaxDynamicSharedMemorySize,
                         SMEM_BYTES);
    kan_kernel<<<256, 256, SMEM_BYTES>>>(x, (float*)d_out);
}

// round 6
// speedup vs baseline: 1.9149x; 1.0422x over previous
#include <cuda_runtime.h>
#include <cuda_fp16.h>
#include <cstdint>

// ---------------------------------------------------------------------------
// effConvKAN3D as f16 HMMA GEMM, grouped K (14 groups x [8 spline + 1 silu]
// chunks = 126 chunks, K=2016), software-pipelined producer/consumer with
// fragment-ordered B (one LDS.128 per chunk) and register-staged silu.
// ---------------------------------------------------------------------------

#define NF       216
#define NCHUNK   126
#define OSTRIDE  32768

#define B_BYTES    (NCHUNK * 512)             // 64512
#define TILE_OFF   B_BYTES
#define TILE_ELEMS (8 * 3 * 6 * 34)           // 4896 floats
#define AB_OFF     (TILE_OFF + TILE_ELEMS * 4)   // 84096
#define WARP_BYTES 3072                       // A0,A1,stage0,stage1 x 768
#define OFFS_OFF   (AB_OFF + 8 * WARP_BYTES)  // 108672
#define SMEM_BYTES (OFFS_OFF + 224 * 4)       // 109568

__device__ __align__(16) uint32_t g_Bf[NCHUNK * 128];   // fragment-ordered B
__device__ __align__(16) uint32_t g_offs[224];

// logical B value at (o, k) in the grouped layout
__device__ __forceinline__ float bval(int o, int k,
                                      const float* __restrict__ bw,
                                      const float* __restrict__ sw,
                                      const float* __restrict__ sc) {
    int g = k / 144, rem = k - 144 * g;
    int w = rem >> 4, col = rem & 15;
    if (w < 8) {                                   // spline chunk
        int f = 16 * g + 2 * w + (col >> 3), c = col & 7;
        return (f < NF) ? sw[(o * NF + f) * 8 + c] * sc[o * NF + f] : 0.0f;
    }
    int f = 16 * g + 2 * (col & 7) + (col >> 3);   // silu chunk
    return (f < NF) ? bw[o * NF + f] : 0.0f;
}

__global__ void prep_kernel(const float* __restrict__ bw,
                            const float* __restrict__ sw,
                            const float* __restrict__ sc) {
    int t = blockIdx.x * 256 + threadIdx.x;
    if (t < 224) {
        uint32_t off = 0;
        if (t < NF) {
            int c = t / 27, r = t - c * 27;
            int dz = r / 9,  r2 = r - dz * 9;
            int dy = r2 / 3, dx = r2 - dy * 3;
            off = (uint32_t)((((c * 3 + dz) * 6 + dy) * 34 + dx) * 4);
        }
        g_offs[t] = off;
    }
    if (t < NCHUNK * 128) {
        int wd = t & 3, lane = (t >> 2) & 31, kc = t >> 7;
        int g8 = lane >> 2, t4 = lane & 3;
        int o = g8 + ((wd >> 1) << 3);
        int kb = kc * 16 + ((wd & 1) << 3) + 2 * t4;
        __half2 h = __floats2half2_rn(bval(o, kb, bw, sw, sc),
                                      bval(o, kb + 1, bw, sw, sc));
        g_Bf[t] = *(uint32_t*)&h;
    }
}

#define MMA2(A0, A1, A2, A3, B0, B1, B2, B3) do {                             \
    asm volatile("mma.sync.aligned.m16n8k16.row.col.f32.f16.f16.f32 "         \
        "{%0,%1,%2,%3}, {%4,%5,%6,%7}, {%8,%9}, {%0,%1,%2,%3};"               \
        : "+f"(d00), "+f"(d01), "+f"(d02), "+f"(d03)                          \
        : "r"(A0), "r"(A1), "r"(A2), "r"(A3), "r"(B0), "r"(B1));              \
    asm volatile("mma.sync.aligned.m16n8k16.row.col.f32.f16.f16.f32 "         \
        "{%0,%1,%2,%3}, {%4,%5,%6,%7}, {%8,%9}, {%0,%1,%2,%3};"               \
        : "+f"(d10), "+f"(d11), "+f"(d12), "+f"(d13)                          \
        : "r"(A0), "r"(A1), "r"(A2), "r"(A3), "r"(B2), "r"(B3));              \
} while (0)

__global__ __launch_bounds__(256, 2)
void kan_kernel(const float* __restrict__ x, float* __restrict__ out) {
    extern __shared__ char smem[];
    const int tid = threadIdx.x;
    const int bid = blockIdx.x;

    for (int i = tid; i < B_BYTES / 16; i += 256)
        ((uint4*)smem)[i] = ((const uint4*)g_Bf)[i];
    if (tid < 224)
        ((uint32_t*)(smem + OFFS_OFF))[tid] = g_offs[tid];

    // x halo tile: [c 8][zz 3][yy 6][xx 34], zero padded
    const int z0 = bid >> 3, y0 = (bid & 7) * 4;
    float* tile = (float*)(smem + TILE_OFF);
    for (int i = tid; i < TILE_ELEMS; i += 256) {
        int c  = i / 612;
        int r1 = i - c * 612;
        int zz = r1 / 204;
        int r2 = r1 - zz * 204;
        int yy = r2 / 34;
        int xx = r2 - yy * 34;
        int gz = z0 - 1 + zz, gy = y0 - 1 + yy, gx = xx - 1;
        float v = 0.0f;
        if (((unsigned)gz < 32u) & ((unsigned)gy < 32u) & ((unsigned)gx < 32u))
            v = __ldg(x + ((c * 32 + gz) * 32 + gy) * 32 + gx);
        tile[i] = v;
    }
    __syncthreads();

    const int wid = tid >> 5, lane = tid & 31;
    const int r = lane & 15, s = lane >> 4;          // producer role
    const int yl = wid >> 1;
    const int xw = (wid & 1) * 16 + r;
    const uint32_t laneBase = (uint32_t)((yl * 34 + xw) * 4);
    const uint32_t* sOffs = (const uint32_t*)(smem + OFFS_OFF);
    const char* tileB = (const char*)tile;
    char* warpA = smem + AB_OFF + wid * WARP_BYTES;  // A0 A1 stage0 stage1
    char* stageB = warpA + 1536;
    const char* sBf = smem;

    const int g8 = lane >> 2, t4 = lane & 3;         // mma fragment role
    const int aO0 = g8 * 48 + t4 * 4;
    const int aO1 = aO0 + 384;

    float d00 = 0, d01 = 0, d02 = 0, d03 = 0;
    float d10 = 0, d11 = 0, d12 = 0, d13 = 0;

    uint32_t sil[4];
    __half hprev = __float2half_rn(0.0f);

    #pragma unroll 1
    for (int g = 0; g < 14; g++) {
        #pragma unroll
        for (int w = 0; w < 8; w++) {
            const int kc = 9 * g + w;
            // ---- consumer loads (chunk kc-1) ----
            uint32_t ca0 = 0, ca1 = 0, ca2 = 0, ca3 = 0;
            uint4 cbf = make_uint4(0, 0, 0, 0);
            const bool doC = (w > 0) || (g > 0);
            if (doC) {
                const char* Abase = (w == 0)
                    ? stageB + ((g - 1) & 1) * 768          // prev = silu chunk
                    : warpA + ((kc - 1) & 1) * 768;
                ca0 = *(const uint32_t*)(Abase + aO0);
                ca1 = *(const uint32_t*)(Abase + aO1);
                ca2 = *(const uint32_t*)(Abase + aO0 + 16);
                ca3 = *(const uint32_t*)(Abase + aO1 + 16);
                cbf = *(const uint4*)(sBf + (kc - 1) * 512 + lane * 16);
            }

            // ---- producer compute (chunk kc) ----
            const int f = 16 * g + 2 * w + s;
            uint32_t off = sOffs[f];
            float v = *(const float*)(tileB + off + laneBase);

            float sv = __fdividef(v, 1.0f + __expf(-v));
            __half hcur = __float2half_rn(sv);
            if (w & 1) {
                __half2 hp = __halves2half2(hprev, hcur);
                sil[w >> 1] = *(uint32_t*)&hp;
            } else {
                hprev = hcur;
            }

            // uniform cubic B-spline, grid [-2.2,2.2], h=0.4, j=0..10
            float tt = fmaf(v, 2.5f, 5.5f);
            float jf = floorf(tt);
            float u = tt - jf;
            int j = (int)jf;
            float u2 = u * u, u3 = u2 * u, om = 1.0f - u;
            float b0 = om * om * om * (1.0f / 6.0f);
            float b1 = fmaf(3.0f, u3, fmaf(-6.0f, u2, 4.0f)) * (1.0f / 6.0f);
            float b2 = fmaf(-3.0f, u3, fmaf(3.0f, u2, fmaf(3.0f, u, 1.0f)))
                       * (1.0f / 6.0f);
            float b3 = u3 * (1.0f / 6.0f);

            __half2 hlo = __floats2half2_rn(b0, b1);
            __half2 hhi = __floats2half2_rn(b2, b3);
            uint32_t lo = *(uint32_t*)&hlo, hi = *(uint32_t*)&hhi;
            if ((unsigned)j > 10u) { lo = 0u; hi = 0u; j = 3; }
            uint64_t B64 = (uint64_t)lo | ((uint64_t)hi << 32);
            int t16 = j - 3;

            uint32_t wv[4];
            #pragma unroll
            for (int i4 = 0; i4 < 4; i4++) {
                int d = 2 * i4 - t16;
                int shc = ((unsigned)d <= 3u) ? d : 0;
                uint32_t a = (uint32_t)(B64 >> (shc * 16));
                wv[i4] = ((unsigned)d <= 3u) ? a : ((d == -1) ? (lo << 16) : 0u);
            }

            // ---- MMA for chunk kc-1 ----
            if (doC) MMA2(ca0, ca1, ca2, ca3, cbf.x, cbf.y, cbf.z, cbf.w);

            // ---- producer stores ----
            *(uint4*)(warpA + (kc & 1) * 768 + r * 48 + s * 16) =
                make_uint4(wv[0], wv[1], wv[2], wv[3]);
            if (w == 7)
                *(uint4*)(stageB + (g & 1) * 768 + r * 48 + s * 16) =
                    make_uint4(sil[0], sil[1], sil[2], sil[3]);
            __syncwarp();
        }
        {   // silu-chunk slot: consume chunk 9g+7 (no produce)
            const int kc = 9 * g + 8;
            const char* Abase = warpA + ((kc - 1) & 1) * 768;
            uint32_t ca0 = *(const uint32_t*)(Abase + aO0);
            uint32_t ca1 = *(const uint32_t*)(Abase + aO1);
            uint32_t ca2 = *(const uint32_t*)(Abase + aO0 + 16);
            uint32_t ca3 = *(const uint32_t*)(Abase + aO1 + 16);
            uint4 cbf = *(const uint4*)(sBf + (kc - 1) * 512 + lane * 16);
            MMA2(ca0, ca1, ca2, ca3, cbf.x, cbf.y, cbf.z, cbf.w);
            __syncwarp();
        }
    }
    {   // drain: consume chunk 125 (silu of group 13) from stage[1]
        const char* Abase = stageB + 768;
        uint32_t ca0 = *(const uint32_t*)(Abase + aO0);
        uint32_t ca1 = *(const uint32_t*)(Abase + aO1);
        uint32_t ca2 = *(const uint32_t*)(Abase + aO0 + 16);
        uint32_t ca3 = *(const uint32_t*)(Abase + aO1 + 16);
        uint4 cbf = *(const uint4*)(sBf + 125 * 512 + lane * 16);
        MMA2(ca0, ca1, ca2, ca3, cbf.x, cbf.y, cbf.z, cbf.w);
    }

    // epilogue
    const int posb = bid * 128 + wid * 16;
    const int pr0 = posb + g8, pr1 = pr0 + 8;
    out[(2 * t4 + 0) * OSTRIDE + pr0] = d00;
    out[(2 * t4 + 1) * OSTRIDE + pr0] = d01;
    out[(2 * t4 + 0) * OSTRIDE + pr1] = d02;
    out[(2 * t4 + 1) * OSTRIDE + pr1] = d03;
    out[(2 * t4 + 8) * OSTRIDE + pr0] = d10;
    out[(2 * t4 + 9) * OSTRIDE + pr0] = d11;
    out[(2 * t4 + 8) * OSTRIDE + pr1] = d12;
    out[(2 * t4 + 9) * OSTRIDE + pr1] = d13;
}

extern "C" void kernel_launch(void* const* d_in, const int* in_sizes, int n_in,
                              void* d_out, int out_size) {
    const float* x  = (const float*)d_in[0];
    const float* bw = (const float*)d_in[1];
    const float* sw = (const float*)d_in[2];
    const float* sc = (const float*)d_in[3];

    prep_kernel<<<63, 256>>>(bw, sw, sc);

    cudaFuncSetAttribute(kan_kernel, cudaFuncAttributeMaxDynamicSharedMemorySize,
                         SMEM_BYTES);
    kan_kernel<<<256, 256, SMEM_BYTES>>>(x, (float*)d_out);
}

// round 8
// speedup vs baseline: 1.9508x; 1.0188x over previous
#include <cuda_runtime.h>
#include <cuda_fp16.h>
#include <cstdint>

// ---------------------------------------------------------------------------
// effConvKAN3D as f16 HMMA GEMM. Grouped K: 14 groups x [8 spline chunks +
// 1 silu chunk] = 126 chunks of 16 (K=2016). Flat 63-slot pipeline: each
// slot produces 2 chunks, consumes the previous slot's 2 (ldmatrix + mma),
// one syncwarp per slot. Two accumulator banks for independent HMMA chains.
// A-tile rows at 32B stride with XOR-swizzled 16B slot (conflict-free STS
// and ldmatrix).
// ---------------------------------------------------------------------------

#define NF       216
#define OSTRIDE  32768

#define B_BYTES    (126 * 512)                // 64512
#define TILE_OFF   B_BYTES
#define TILE_ELEMS (8 * 3 * 6 * 34)           // 4896 floats
#define AB_OFF     (TILE_OFF + TILE_ELEMS * 4)   // 84096
#define WARP_BYTES 3072                       // ring 2x2x512 + 2 stages x512
#define OFFS_OFF   (AB_OFF + 8 * WARP_BYTES)  // 108672
#define SMEM_BYTES (OFFS_OFF + 224 * 4)       // 109568

__device__ __align__(16) uint32_t g_Bf[126 * 128];   // fragment-ordered B
__device__ __align__(16) uint32_t g_offs[224];

__device__ __forceinline__ float bval(int o, int k,
                                      const float* __restrict__ bw,
                                      const float* __restrict__ sw,
                                      const float* __restrict__ sc) {
    int g = k / 144, rem = k - 144 * g;
    int w = rem >> 4, col = rem & 15;
    if (w < 8) {
        int f = 16 * g + 2 * w + (col >> 3), c = col & 7;
        return (f < NF) ? sw[(o * NF + f) * 8 + c] * sc[o * NF + f] : 0.0f;
    }
    int f = 16 * g + 2 * (col & 7) + (col >> 3);
    return (f < NF) ? bw[o * NF + f] : 0.0f;
}

__global__ void prep_kernel(const float* __restrict__ bw,
                            const float* __restrict__ sw,
                            const float* __restrict__ sc) {
    int t = blockIdx.x * 256 + threadIdx.x;
    if (t < 224) {
        uint32_t off = 0;
        if (t < NF) {
            int c = t / 27, r = t - c * 27;
            int dz = r / 9,  r2 = r - dz * 9;
            int dy = r2 / 3, dx = r2 - dy * 3;
            off = (uint32_t)((((c * 3 + dz) * 6 + dy) * 34 + dx) * 4);
        }
        g_offs[t] = off;
    }
    if (t < 126 * 128) {
        int wd = t & 3, lane = (t >> 2) & 31, kc = t >> 7;
        int g8 = lane >> 2, t4 = lane & 3;
        int o = g8 + ((wd >> 1) << 3);
        int kb = kc * 16 + ((wd & 1) << 3) + 2 * t4;
        __half2 h = __floats2half2_rn(bval(o, kb, bw, sw, sc),
                                      bval(o, kb + 1, bw, sw, sc));
        g_Bf[t] = *(uint32_t*)&h;
    }
}

// ---- slot building blocks -------------------------------------------------
#define PRODUCE(FB, W, STADDR) do {                                           \
    const int f_ = (FB) + s;                                                  \
    uint32_t off_ = sOffs[f_];                                                \
    float v_ = *(const float*)(tileB + off_ + laneBase);                      \
    float sv_ = __fdividef(v_, 1.0f + __expf(-v_));                           \
    __half hc_ = __float2half_rn(sv_);                                        \
    if ((W) & 1) { __half2 hp_ = __halves2half2(hprev, hc_);                  \
                   sil[(W) >> 1] = *(uint32_t*)&hp_; }                        \
    else hprev = hc_;                                                         \
    float tt_ = fmaf(v_, 2.5f, 5.5f);                                         \
    float jf_ = floorf(tt_);                                                  \
    float u_ = tt_ - jf_;                                                     \
    int j_ = (int)jf_;                                                        \
    float u2_ = u_ * u_, u3_ = u2_ * u_, om_ = 1.0f - u_;                     \
    float b0_ = om_ * om_ * om_ * (1.0f / 6.0f);                              \
    float b1_ = fmaf(3.0f, u3_, fmaf(-6.0f, u2_, 4.0f)) * (1.0f / 6.0f);      \
    float b2_ = fmaf(-3.0f, u3_, fmaf(3.0f, u2_, fmaf(3.0f, u_, 1.0f)))       \
                * (1.0f / 6.0f);                                              \
    float b3_ = u3_ * (1.0f / 6.0f);                                          \
    __half2 hlo_ = __floats2half2_rn(b0_, b1_);                               \
    __half2 hhi_ = __floats2half2_rn(b2_, b3_);                               \
    uint32_t lo_ = *(uint32_t*)&hlo_, hi_ = *(uint32_t*)&hhi_;                \
    if ((unsigned)j_ > 10u) { lo_ = 0u; hi_ = 0u; j_ = 3; }                   \
    uint64_t B64_ = (uint64_t)lo_ | ((uint64_t)hi_ << 32);                    \
    int t16_ = j_ - 3;                                                        \
    uint32_t wv_[4];                                                          \
    _Pragma("unroll")                                                         \
    for (int i4_ = 0; i4_ < 4; i4_++) {                                       \
        int d_ = 2 * i4_ - t16_;                                              \
        int shc_ = ((unsigned)d_ <= 3u) ? d_ : 0;                             \
        uint32_t a_ = (uint32_t)(B64_ >> (shc_ * 16));                        \
        wv_[i4_] = ((unsigned)d_ <= 3u) ? a_ : ((d_ == -1) ? (lo_ << 16) : 0u);\
    }                                                                         \
    asm volatile("st.shared.v4.b32 [%0], {%1,%2,%3,%4};"                      \
        :: "r"((STADDR) + po), "r"(wv_[0]), "r"(wv_[1]), "r"(wv_[2]),         \
           "r"(wv_[3]) : "memory");                                           \
} while (0)

#define DUMPSTAGE(STADDR)                                                     \
    asm volatile("st.shared.v4.b32 [%0], {%1,%2,%3,%4};"                      \
        :: "r"((STADDR) + po), "r"(sil[0]), "r"(sil[1]), "r"(sil[2]),         \
           "r"(sil[3]) : "memory")

#define CONSUME(AADDR, BOFF, BK) do {                                         \
    uint32_t a0_, a1_, a2_, a3_;                                              \
    asm volatile("ldmatrix.sync.aligned.m8n8.x4.shared.b16 "                  \
        "{%0,%1,%2,%3}, [%4];"                                                \
        : "=r"(a0_), "=r"(a1_), "=r"(a2_), "=r"(a3_) : "r"((AADDR) + co));    \
    uint4 cb_ = *(const uint4*)(pB + (BOFF));                                 \
    asm volatile("mma.sync.aligned.m16n8k16.row.col.f32.f16.f16.f32 "         \
        "{%0,%1,%2,%3}, {%4,%5,%6,%7}, {%8,%9}, {%0,%1,%2,%3};"               \
        : "+f"(d##BK[0]), "+f"(d##BK[1]), "+f"(d##BK[2]), "+f"(d##BK[3])      \
        : "r"(a0_), "r"(a1_), "r"(a2_), "r"(a3_), "r"(cb_.x), "r"(cb_.y));    \
    asm volatile("mma.sync.aligned.m16n8k16.row.col.f32.f16.f16.f32 "         \
        "{%0,%1,%2,%3}, {%4,%5,%6,%7}, {%8,%9}, {%0,%1,%2,%3};"               \
        : "+f"(d##BK[4]), "+f"(d##BK[5]), "+f"(d##BK[6]), "+f"(d##BK[7])      \
        : "r"(a0_), "r"(a1_), "r"(a2_), "r"(a3_), "r"(cb_.z), "r"(cb_.w));    \
} while (0)

__global__ __launch_bounds__(256, 2)
void kan_kernel(const float* __restrict__ x, float* __restrict__ out) {
    extern __shared__ char smem[];
    const int tid = threadIdx.x;
    const int bid = blockIdx.x;

    for (int i = tid; i < B_BYTES / 16; i += 256)
        ((uint4*)smem)[i] = ((const uint4*)g_Bf)[i];
    if (tid < 224)
        ((uint32_t*)(smem + OFFS_OFF))[tid] = g_offs[tid];

    // x halo tile: [c 8][zz 3][yy 6][xx 34], zero padded
    const int z0 = bid >> 3, y0 = (bid & 7) * 4;
    float* tile = (float*)(smem + TILE_OFF);
    for (int i = tid; i < TILE_ELEMS; i += 256) {
        int c  = i / 612;
        int r1 = i - c * 612;
        int zz = r1 / 204;
        int r2 = r1 - zz * 204;
        int yy = r2 / 34;
        int xx = r2 - yy * 34;
        int gz = z0 - 1 + zz, gy = y0 - 1 + yy, gx = xx - 1;
        float v = 0.0f;
        if (((unsigned)gz < 32u) & ((unsigned)gy < 32u) & ((unsigned)gx < 32u))
            v = __ldg(x + ((c * 32 + gz) * 32 + gy) * 32 + gx);
        tile[i] = v;
    }
    __syncthreads();

    const int wid = tid >> 5, lane = tid & 31;
    const int r = lane & 15, s = lane >> 4;
    const int yl = wid >> 1;
    const int xw = (wid & 1) * 16 + r;
    const uint32_t laneBase = (uint32_t)((yl * 34 + xw) * 4);
    const uint32_t* sOffs = (const uint32_t*)(smem + OFFS_OFF);
    const char* tileB = (const char*)tile;

    uint32_t sb;
    asm("{ .reg .u64 t; cvta.to.shared.u64 t, %1; cvt.u32.u64 %0, t; }"
        : "=r"(sb) : "l"(smem));
    const uint32_t warpRing = sb + AB_OFF + wid * WARP_BYTES;
    const uint32_t stA = warpRing + 2048, stB = warpRing + 2560;
    // XOR-swizzled A layout: row*32 + (khalf ^ ((row>>2)&1))*16  (conflict-free)
    const uint32_t po = (uint32_t)(r * 32 + ((s ^ ((r >> 2) & 1)) << 4));
    const uint32_t co = (uint32_t)((lane & 15) * 32 +
                        (((((lane >> 4) & 1)) ^ (((lane & 15) >> 2) & 1)) << 4));

    const int g8 = lane >> 2, t4 = lane & 3;

    float dE[8], dO[8];
    #pragma unroll
    for (int i = 0; i < 8; i++) { dE[i] = 0.0f; dO[i] = 0.0f; }
    uint32_t sil[4];
    __half hprev = __float2half_rn(0.0f);
    const char* sBf_lane = smem + lane * 16;

    #pragma unroll 1
    for (int t = 0; t < 7; t++) {
        const int F0 = 32 * t, F1 = F0 + 16;
        const uint32_t pbA = warpRing + ((t & 1) << 10);
        const uint32_t pbB = warpRing + (((t + 1) & 1) << 10);
        const char* pB = sBf_lane + t * 9216;

        // s0: produce chunks 0,1 ; consume prev (-2 ring, -1 = silu stageB)
        if (t) {
            CONSUME(pbB, -1024, E);
            CONSUME(stB, -512, O);
        }
        PRODUCE(F0 + 0, 0, pbA);
        PRODUCE(F0 + 2, 1, pbA + 512);
        __syncwarp();
        // s1
        CONSUME(pbA, 0, E);
        CONSUME(pbA + 512, 512, O);
        PRODUCE(F0 + 4, 2, pbB);
        PRODUCE(F0 + 6, 3, pbB + 512);
        __syncwarp();
        // s2
        CONSUME(pbB, 1024, E);
        CONSUME(pbB + 512, 1536, O);
        PRODUCE(F0 + 8, 4, pbA);
        PRODUCE(F0 + 10, 5, pbA + 512);
        __syncwarp();
        // s3 (+ stageA dump)
        CONSUME(pbA, 2048, E);
        CONSUME(pbA + 512, 2560, O);
        PRODUCE(F0 + 12, 6, pbB);
        PRODUCE(F0 + 14, 7, pbB + 512);
        DUMPSTAGE(stA);
        __syncwarp();
        // s4: single produce (chunk w=0 of group 2t+1)
        CONSUME(pbB, 3072, E);
        CONSUME(pbB + 512, 3584, O);
        PRODUCE(F1 + 0, 0, pbA + 512);
        __syncwarp();
        // s5: consume silu A (stageA) + chunk 18t+9
        CONSUME(stA, 4096, E);
        CONSUME(pbA + 512, 4608, O);
        PRODUCE(F1 + 2, 1, pbB);
        PRODUCE(F1 + 4, 2, pbB + 512);
        __syncwarp();
        // s6
        CONSUME(pbB, 5120, E);
        CONSUME(pbB + 512, 5632, O);
        PRODUCE(F1 + 6, 3, pbA);
        PRODUCE(F1 + 8, 4, pbA + 512);
        __syncwarp();
        // s7
        CONSUME(pbA, 6144, E);
        CONSUME(pbA + 512, 6656, O);
        PRODUCE(F1 + 10, 5, pbB);
        PRODUCE(F1 + 12, 6, pbB + 512);
        __syncwarp();
        // s8 (+ stageB dump)
        CONSUME(pbB, 7168, E);
        CONSUME(pbB + 512, 7680, O);
        PRODUCE(F1 + 14, 7, pbA);
        DUMPSTAGE(stB);
        __syncwarp();
    }
    // drain: chunk 124 (ring buf of t=6, offset 0) and 125 (silu, stageB)
    {
        const char* pB = sBf_lane + 124 * 512;
        CONSUME(warpRing, 0, E);
        CONSUME(stB, 512, O);
    }

    // epilogue
    const int posb = bid * 128 + wid * 16;
    const int pr0 = posb + g8, pr1 = pr0 + 8;
    out[(2 * t4 + 0) * OSTRIDE + pr0] = dE[0] + dO[0];
    out[(2 * t4 + 1) * OSTRIDE + pr0] = dE[1] + dO[1];
    out[(2 * t4 + 0) * OSTRIDE + pr1] = dE[2] + dO[2];
    out[(2 * t4 + 1) * OSTRIDE + pr1] = dE[3] + dO[3];
    out[(2 * t4 + 8) * OSTRIDE + pr0] = dE[4] + dO[4];
    out[(2 * t4 + 9) * OSTRIDE + pr0] = dE[5] + dO[5];
    out[(2 * t4 + 8) * OSTRIDE + pr1] = dE[6] + dO[6];
    out[(2 * t4 + 9) * OSTRIDE + pr1] = dE[7] + dO[7];
}

extern "C" void kernel_launch(void* const* d_in, const int* in_sizes, int n_in,
                              void* d_out, int out_size) {
    const float* x  = (const float*)d_in[0];
    const float* bw = (const float*)d_in[1];
    const float* sw = (const float*)d_in[2];
    const float* sc = (const float*)d_in[3];

    prep_kernel<<<63, 256>>>(bw, sw, sc);

    cudaFuncSetAttribute(kan_kernel, cudaFuncAttributeMaxDynamicSharedMemorySize,
                         SMEM_BYTES);
    kan_kernel<<<256, 256, SMEM_BYTES>>>(x, (float*)d_out);
}

// round 10
// speedup vs baseline: 2.0284x; 1.0398x over previous
#include <cuda_runtime.h>
#include <cuda_fp16.h>
#include <cstdint>

// ---------------------------------------------------------------------------
// effConvKAN3D as f16 HMMA GEMM with globally precomputed basis rows.
// K layout: chunks 0..107 spline (f = 2*kc + col/8, c = col%8),
//           chunks 108..121 silu (f = 16*(kc-108)+col). K = 1952.
// prep_basis: per halo-padded x value (8x34^3) the packed 8-half basis row;
// halo entries hold basis(0.0) to match the reference's zero padding.
// Main kernel: spline A-production = LDG.128 of the precomputed row + STS.128.
// ---------------------------------------------------------------------------

#define NF       216
#define OSTRIDE  32768
#define NCH      122

#define B_BYTES   (NCH * 512)               // 62464
#define SIL_OFF   B_BYTES                   // silu tile: 5040 halves (incl pad)
#define SIL_BYTES (5040 * 2)                // 10080
#define RING_OFF  (SIL_OFF + SIL_BYTES)     // 72544
#define OFFB_OFF  (RING_OFF + 8 * 2048)     // 88928
#define OFFS_OFF  (OFFB_OFF + 216 * 4)      // 89792
#define SMEM_BYTES (OFFS_OFF + 224 * 2)     // 90240

__device__ __align__(16) uint4    g_basis[8 * 34 * 34 * 34];  // packed rows
__device__ __align__(16) uint32_t g_Bf[NCH * 128];            // fragment B
__device__ uint32_t g_offB[216];
__device__ uint16_t g_offS[224];

// packed 8-half basis row for value v (uniform cubic B-spline, grid
// [-2.2,2.2], h=0.4, intervals j=0..10, window j-3..j clipped to 0..7)
__device__ __forceinline__ uint4 basis_row(float v) {
    float tt = fmaf(v, 2.5f, 5.5f);
    float jf = floorf(tt);
    float u = tt - jf;
    int j = (int)jf;
    float u2 = u * u, u3 = u2 * u, om = 1.0f - u;
    float b0 = om * om * om * (1.0f / 6.0f);
    float b1 = fmaf(3.0f, u3, fmaf(-6.0f, u2, 4.0f)) * (1.0f / 6.0f);
    float b2 = fmaf(-3.0f, u3, fmaf(3.0f, u2, fmaf(3.0f, u, 1.0f))) * (1.0f / 6.0f);
    float b3 = u3 * (1.0f / 6.0f);
    __half2 hlo = __floats2half2_rn(b0, b1);
    __half2 hhi = __floats2half2_rn(b2, b3);
    uint32_t lo = *(uint32_t*)&hlo, hi = *(uint32_t*)&hhi;
    if ((unsigned)j > 10u) { lo = 0u; hi = 0u; j = 3; }
    uint64_t B64 = (uint64_t)lo | ((uint64_t)hi << 32);
    int t16 = j - 3;
    uint32_t wv[4];
    #pragma unroll
    for (int i = 0; i < 4; i++) {
        int d = 2 * i - t16;
        int shc = ((unsigned)d <= 3u) ? d : 0;
        uint32_t a = (uint32_t)(B64 >> (shc * 16));
        wv[i] = ((unsigned)d <= 3u) ? a : ((d == -1) ? (lo << 16) : 0u);
    }
    return make_uint4(wv[0], wv[1], wv[2], wv[3]);
}

__global__ void prep_basis(const float* __restrict__ x) {
    int idx = blockIdx.x * 256 + threadIdx.x;
    if (idx >= 8 * 34 * 34 * 34) return;
    int c  = idx / 39304;
    int r1 = idx - c * 39304;
    int iz = r1 / 1156;
    int r2 = r1 - iz * 1156;
    int iy = r2 / 34;
    int ix = r2 - iy * 34;
    int az = iz - 1, ay = iy - 1, ax = ix - 1;
    float v = 0.0f;   // reference zero-pads x, then evaluates basis(0) there
    if (((unsigned)az < 32u) & ((unsigned)ay < 32u) & ((unsigned)ax < 32u))
        v = x[((c * 32 + az) * 32 + ay) * 32 + ax];
    g_basis[idx] = basis_row(v);
}

// logical B value at (o, k)
__device__ __forceinline__ float bval(int o, int k,
                                      const float* __restrict__ bw,
                                      const float* __restrict__ sw,
                                      const float* __restrict__ sc) {
    int kc = k >> 4, col = k & 15;
    if (kc < 108) {
        int f = 2 * kc + (col >> 3), c = col & 7;
        return sw[(o * NF + f) * 8 + c] * sc[o * NF + f];
    }
    int f = 16 * (kc - 108) + col;
    return (f < NF) ? bw[o * NF + f] : 0.0f;
}

__global__ void prep_kernel(const float* __restrict__ bw,
                            const float* __restrict__ sw,
                            const float* __restrict__ sc) {
    int t = blockIdx.x * 256 + threadIdx.x;
    if (t < 224) {
        int c = t / 27, r = t - c * 27;
        int dz = r / 9,  r2 = r - dz * 9;
        int dy = r2 / 3, dx = r2 - dy * 3;
        if (t < 216) g_offB[t] = (uint32_t)((c * 39304 + dz * 1156 + dy * 34 + dx) * 16);
        g_offS[t] = (t < NF)
            ? (uint16_t)((((c * 3 + dz) * 6 + dy) * 34 + dx) * 2)
            : (uint16_t)(4896 * 2);   // zero-pad region
    }
    if (t < NCH * 128) {
        int wd = t & 3, lane = (t >> 2) & 31, kc = t >> 7;
        int g8 = lane >> 2, t4 = lane & 3;
        int o = g8 + ((wd >> 1) << 3);
        int kb = kc * 16 + ((wd & 1) << 3) + 2 * t4;
        __half2 h = __floats2half2_rn(bval(o, kb, bw, sw, sc),
                                      bval(o, kb + 1, bw, sw, sc));
        g_Bf[t] = *(uint32_t*)&h;
    }
}

#define CONSUME(AADDR, BPTR, BK) do {                                         \
    uint32_t a0_, a1_, a2_, a3_;                                              \
    asm volatile("ldmatrix.sync.aligned.m8n8.x4.shared.b16 "                  \
        "{%0,%1,%2,%3}, [%4];"                                                \
        : "=r"(a0_), "=r"(a1_), "=r"(a2_), "=r"(a3_) : "r"((AADDR) + co));    \
    uint4 cb_ = *(const uint4*)(BPTR);                                        \
    asm volatile("mma.sync.aligned.m16n8k16.row.col.f32.f16.f16.f32 "         \
        "{%0,%1,%2,%3}, {%4,%5,%6,%7}, {%8,%9}, {%0,%1,%2,%3};"               \
        : "+f"(d##BK[0]), "+f"(d##BK[1]), "+f"(d##BK[2]), "+f"(d##BK[3])      \
        : "r"(a0_), "r"(a1_), "r"(a2_), "r"(a3_), "r"(cb_.x), "r"(cb_.y));    \
    asm volatile("mma.sync.aligned.m16n8k16.row.col.f32.f16.f16.f32 "         \
        "{%0,%1,%2,%3}, {%4,%5,%6,%7}, {%8,%9}, {%0,%1,%2,%3};"               \
        : "+f"(d##BK[4]), "+f"(d##BK[5]), "+f"(d##BK[6]), "+f"(d##BK[7])      \
        : "r"(a0_), "r"(a1_), "r"(a2_), "r"(a3_), "r"(cb_.z), "r"(cb_.w));    \
} while (0)

#define STS128(DST, V)                                                        \
    asm volatile("st.shared.v4.b32 [%0], {%1,%2,%3,%4};"                      \
        :: "r"(DST), "r"((V).x), "r"((V).y), "r"((V).z), "r"((V).w) : "memory")

#define SILU_CHUNK(G, DST) do {                                               \
    uint4 ov_ = *(const uint4*)(smem + OFFS_OFF + ((G) * 16 + s * 8) * 2);    \
    const uint16_t* o16_ = (const uint16_t*)&ov_;                             \
    uint32_t w_[4];                                                           \
    _Pragma("unroll")                                                         \
    for (int i_ = 0; i_ < 4; i_++) {                                          \
        __half h0_ = *(const __half*)(silT + o16_[2 * i_] + laneBaseS);       \
        __half h1_ = *(const __half*)(silT + o16_[2 * i_ + 1] + laneBaseS);   \
        __half2 hp_ = __halves2half2(h0_, h1_);                               \
        w_[i_] = *(uint32_t*)&hp_;                                            \
    }                                                                         \
    asm volatile("st.shared.v4.b32 [%0], {%1,%2,%3,%4};"                      \
        :: "r"(DST), "r"(w_[0]), "r"(w_[1]), "r"(w_[2]), "r"(w_[3])           \
        : "memory");                                                          \
} while (0)

__global__ __launch_bounds__(256, 2)
void kan_kernel(const float* __restrict__ x, float* __restrict__ out) {
    extern __shared__ char smem[];
    const int tid = threadIdx.x;
    const int bid = blockIdx.x;

    // B tile + offset tables
    for (int i = tid; i < B_BYTES / 16; i += 256)
        ((uint4*)smem)[i] = ((const uint4*)g_Bf)[i];
    if (tid < 216) ((uint32_t*)(smem + OFFB_OFF))[tid] = g_offB[tid];
    if (tid < 112) ((uint32_t*)(smem + OFFS_OFF))[tid] = ((const uint32_t*)g_offS)[tid];

    // silu tile: [c 8][zz 3][yy 6][xx 34] + 144-half zero pad
    const int z0 = bid >> 3, y0 = (bid & 7) * 4;
    __half* sil = (__half*)(smem + SIL_OFF);
    for (int i = tid; i < 5040; i += 256) {
        float sv = 0.0f;
        if (i < 4896) {
            int c  = i / 612;
            int r1 = i - c * 612;
            int zz = r1 / 204;
            int r2 = r1 - zz * 204;
            int yy = r2 / 34;
            int xx = r2 - yy * 34;
            int gz = z0 - 1 + zz, gy = y0 - 1 + yy, gx = xx - 1;
            if (((unsigned)gz < 32u) & ((unsigned)gy < 32u) & ((unsigned)gx < 32u)) {
                float v = __ldg(x + ((c * 32 + gz) * 32 + gy) * 32 + gx);
                sv = __fdividef(v, 1.0f + __expf(-v));
            }
        }
        sil[i] = __float2half_rn(sv);
    }
    __syncthreads();

    const int wid = tid >> 5, lane = tid & 31;
    const int r = lane & 15, s = lane >> 4;
    const int yl = wid >> 1;
    const int xw = (wid & 1) * 16 + r;
    const uint32_t laneBaseB = (uint32_t)((z0 * 1156 + (y0 + yl) * 34 + xw) * 16);
    const uint32_t laneBaseS = (uint32_t)((yl * 34 + xw) * 2);
    const uint32_t* sOffB = (const uint32_t*)(smem + OFFB_OFF);
    const char* silT = smem + SIL_OFF;
    const char* sBf_lane = smem + lane * 16;

    uint32_t sb;
    asm("{ .reg .u64 t; cvta.to.shared.u64 t, %1; cvt.u32.u64 %0, t; }"
        : "=r"(sb) : "l"(smem));
    const uint32_t warpRing = sb + RING_OFF + wid * 2048;
    // XOR-swizzled A layout (validated R8): row*32 + (khalf ^ ((row>>2)&1))*16
    const uint32_t po = (uint32_t)(r * 32 + ((s ^ ((r >> 2) & 1)) << 4));
    const uint32_t co = (uint32_t)((lane & 15) * 32 +
                        ((((lane >> 4) & 1) ^ (((lane & 15) >> 2) & 1)) << 4));

    const int g8 = lane >> 2, t4 = lane & 3;

    float dE[8], dO[8];
    #pragma unroll
    for (int i = 0; i < 8; i++) { dE[i] = 0.0f; dO[i] = 0.0f; }

    const char* gB = (const char*)g_basis;
    // prefetch slots 0 and 1 (chunk features 4t+s, 4t+2+s)
    uint4 q0a = *(const uint4*)(gB + sOffB[s]     + laneBaseB);
    uint4 q0b = *(const uint4*)(gB + sOffB[2 + s] + laneBaseB);
    uint4 q1a = *(const uint4*)(gB + sOffB[4 + s] + laneBaseB);
    uint4 q1b = *(const uint4*)(gB + sOffB[6 + s] + laneBaseB);

    #pragma unroll 1
    for (int t = 0; t < 61; t++) {
        if (t > 0) {
            const int u = t - 1;
            const int kc0 = (u < 54) ? 2 * u : 108 + 2 * (u - 54);
            const char* bp = sBf_lane + kc0 * 512;
            const uint32_t ab = warpRing + ((u & 1) << 10);
            CONSUME(ab, bp, E);
            CONSUME(ab + 512, bp + 512, O);
        }
        const uint32_t dst = warpRing + ((t & 1) << 10);
        if (t < 54) {
            STS128(dst + po, q0a);
            STS128(dst + 512 + po, q0b);
            q0a = q1a; q0b = q1b;
            if (t + 2 < 54) {
                const int f = 4 * (t + 2) + s;
                q1a = *(const uint4*)(gB + sOffB[f]     + laneBaseB);
                q1b = *(const uint4*)(gB + sOffB[f + 2] + laneBaseB);
            }
        } else {
            const int g0 = 2 * (t - 54);
            SILU_CHUNK(g0, dst + po);
            SILU_CHUNK(g0 + 1, dst + 512 + po);
        }
        __syncwarp();
    }
    {   // drain: slot 60 = chunks 120, 121
        const char* bp = sBf_lane + 120 * 512;
        const uint32_t ab = warpRing + ((60 & 1) << 10);
        CONSUME(ab, bp, E);
        CONSUME(ab + 512, bp + 512, O);
    }

    // epilogue
    const int posb = bid * 128 + wid * 16;
    const int pr0 = posb + g8, pr1 = pr0 + 8;
    out[(2 * t4 + 0) * OSTRIDE + pr0] = dE[0] + dO[0];
    out[(2 * t4 + 1) * OSTRIDE + pr0] = dE[1] + dO[1];
    out[(2 * t4 + 0) * OSTRIDE + pr1] = dE[2] + dO[2];
    out[(2 * t4 + 1) * OSTRIDE + pr1] = dE[3] + dO[3];
    out[(2 * t4 + 8) * OSTRIDE + pr0] = dE[4] + dO[4];
    out[(2 * t4 + 9) * OSTRIDE + pr0] = dE[5] + dO[5];
    out[(2 * t4 + 8) * OSTRIDE + pr1] = dE[6] + dO[6];
    out[(2 * t4 + 9) * OSTRIDE + pr1] = dE[7] + dO[7];
}

extern "C" void kernel_launch(void* const* d_in, const int* in_sizes, int n_in,
                              void* d_out, int out_size) {
    const float* x  = (const float*)d_in[0];
    const float* bw = (const float*)d_in[1];
    const float* sw = (const float*)d_in[2];
    const float* sc = (const float*)d_in[3];

    prep_kernel<<<(NCH * 128 + 255) / 256, 256>>>(bw, sw, sc);
    prep_basis<<<(8 * 34 * 34 * 34 + 255) / 256, 256>>>(x);

    cudaFuncSetAttribute(kan_kernel, cudaFuncAttributeMaxDynamicSharedMemorySize,
                         SMEM_BYTES);
    kan_kernel<<<256, 256, SMEM_BYTES>>>(x, (float*)d_out);
}

// round 12
// speedup vs baseline: 2.1397x; 1.0548x over previous
#include <cuda_runtime.h>
#include <cuda_fp16.h>
#include <cstdint>

// ---------------------------------------------------------------------------
// effConvKAN3D as f16 HMMA GEMM, A fragments loaded DIRECTLY from global
// precomputed arrays (no smem staging, no syncwarp in the main loop).
//   chunks 0..107: spline, k0..7 = basis row of f=2kc, k8..15 = f=2kc+1
//   chunks 108..121: silu, k col = feature 16g+col (g = kc-108)
// g_basis[c][iz][iy][ix] : packed 8-half basis row (halo = basis(0))
// g_sil2[p][pos]         : half2( silu f=2p, silu f=2p+1 ), p>=108 zero
// ---------------------------------------------------------------------------

#define NF      216
#define OSTRIDE 32768
#define NCH     122
#define PSZ     131072              // bytes per silu pair plane (32768 * 4)

#define B_BYTES (NCH * 512)         // 62464 — the ONLY smem use
#define B_U4    (B_BYTES / 16)      // 3904 uint4

#define NB_ITEMS   (NCH * 128)            // 15616
#define NBAS_ITEMS (8 * 34 * 34 * 34)     // 314432
#define NSIL_ITEMS (112 * 32768)          // 3670016
#define PREP_TOTAL (NB_ITEMS + NBAS_ITEMS + NSIL_ITEMS)

__device__ __align__(16) uint4    g_basis[NBAS_ITEMS];
__device__ __align__(16) uint32_t g_Bf[NB_ITEMS];
__device__ __align__(16) uint32_t g_sil2[NSIL_ITEMS];

// packed 8-half basis row (uniform cubic B-spline, grid [-2.2,2.2], h=0.4)
__device__ __forceinline__ uint4 basis_row(float v) {
    float tt = fmaf(v, 2.5f, 5.5f);
    float jf = floorf(tt);
    float u = tt - jf;
    int j = (int)jf;
    float u2 = u * u, u3 = u2 * u, om = 1.0f - u;
    float b0 = om * om * om * (1.0f / 6.0f);
    float b1 = fmaf(3.0f, u3, fmaf(-6.0f, u2, 4.0f)) * (1.0f / 6.0f);
    float b2 = fmaf(-3.0f, u3, fmaf(3.0f, u2, fmaf(3.0f, u, 1.0f))) * (1.0f / 6.0f);
    float b3 = u3 * (1.0f / 6.0f);
    __half2 hlo = __floats2half2_rn(b0, b1);
    __half2 hhi = __floats2half2_rn(b2, b3);
    uint32_t lo = *(uint32_t*)&hlo, hi = *(uint32_t*)&hhi;
    if ((unsigned)j > 10u) { lo = 0u; hi = 0u; j = 3; }
    uint64_t B64 = (uint64_t)lo | ((uint64_t)hi << 32);
    int t16 = j - 3;
    uint32_t wv[4];
    #pragma unroll
    for (int i = 0; i < 4; i++) {
        int d = 2 * i - t16;
        int shc = ((unsigned)d <= 3u) ? d : 0;
        uint32_t a = (uint32_t)(B64 >> (shc * 16));
        wv[i] = ((unsigned)d <= 3u) ? a : ((d == -1) ? (lo << 16) : 0u);
    }
    return make_uint4(wv[0], wv[1], wv[2], wv[3]);
}

__device__ __forceinline__ float gatherX(const float* __restrict__ x,
                                         int pos, int f) {
    int z = pos >> 10, y = (pos >> 5) & 31, xc = pos & 31;
    int c = f / 27, r = f - c * 27;
    int dz = r / 9,  r2 = r - dz * 9;
    int dy = r2 / 3, dx = r2 - dy * 3;
    int gz = z + dz - 1, gy = y + dy - 1, gx = xc + dx - 1;
    if (((unsigned)gz < 32u) & ((unsigned)gy < 32u) & ((unsigned)gx < 32u))
        return x[((c * 32 + gz) * 32 + gy) * 32 + gx];
    return 0.0f;
}

__device__ __forceinline__ float bval(int o, int k,
                                      const float* __restrict__ bw,
                                      const float* __restrict__ sw,
                                      const float* __restrict__ sc) {
    int kc = k >> 4, col = k & 15;
    if (kc < 108) {
        int f = 2 * kc + (col >> 3), c = col & 7;
        return sw[(o * NF + f) * 8 + c] * sc[o * NF + f];
    }
    int f = 16 * (kc - 108) + col;
    return (f < NF) ? bw[o * NF + f] : 0.0f;
}

__global__ void prep_all(const float* __restrict__ x,
                         const float* __restrict__ bw,
                         const float* __restrict__ sw,
                         const float* __restrict__ sc) {
    int t = blockIdx.x * 256 + threadIdx.x;
    if (t < NB_ITEMS) {
        int wd = t & 3, lane = (t >> 2) & 31, kc = t >> 7;
        int g8 = lane >> 2, t4 = lane & 3;
        int o = g8 + ((wd >> 1) << 3);
        int kb = kc * 16 + ((wd & 1) << 3) + 2 * t4;
        __half2 h = __floats2half2_rn(bval(o, kb, bw, sw, sc),
                                      bval(o, kb + 1, bw, sw, sc));
        g_Bf[t] = *(uint32_t*)&h;
        return;
    }
    t -= NB_ITEMS;
    if (t < NBAS_ITEMS) {
        int c  = t / 39304;
        int r1 = t - c * 39304;
        int iz = r1 / 1156;
        int r2 = r1 - iz * 1156;
        int iy = r2 / 34;
        int ix = r2 - iy * 34;
        int az = iz - 1, ay = iy - 1, ax = ix - 1;
        float v = 0.0f;    // halo -> basis(0) (reference zero-pads x)
        if (((unsigned)az < 32u) & ((unsigned)ay < 32u) & ((unsigned)ax < 32u))
            v = x[((c * 32 + az) * 32 + ay) * 32 + ax];
        g_basis[t] = basis_row(v);
        return;
    }
    t -= NBAS_ITEMS;
    if (t < NSIL_ITEMS) {
        int p = t >> 15, pos = t & 32767;
        float s0 = 0.0f, s1 = 0.0f;
        int f0 = 2 * p;
        if (f0 < NF) {
            float v = gatherX(x, pos, f0);
            s0 = __fdividef(v, 1.0f + __expf(-v));
        }
        if (f0 + 1 < NF) {
            float v = gatherX(x, pos, f0 + 1);
            s1 = __fdividef(v, 1.0f + __expf(-v));
        }
        __half2 h = __floats2half2_rn(s0, s1);
        g_sil2[t] = *(uint32_t*)&h;
    }
}

// compile-time basis-array offset for feature f (folds under full unroll)
__device__ __forceinline__ uint32_t offB(int f) {
    int c = f / 27, r = f - c * 27;
    int dz = r / 9,  r2 = r - dz * 9;
    int dy = r2 / 3, dx = r2 - dy * 3;
    return (uint32_t)((c * 39304 + dz * 1156 + dy * 34 + dx) * 16);
}

#define MMA2(A0, A1, A2, A3, CB, BK) do {                                     \
    asm volatile("mma.sync.aligned.m16n8k16.row.col.f32.f16.f16.f32 "         \
        "{%0,%1,%2,%3}, {%4,%5,%6,%7}, {%8,%9}, {%0,%1,%2,%3};"               \
        : "+f"(d##BK[0]), "+f"(d##BK[1]), "+f"(d##BK[2]), "+f"(d##BK[3])      \
        : "r"(A0), "r"(A1), "r"(A2), "r"(A3), "r"((CB).x), "r"((CB).y));      \
    asm volatile("mma.sync.aligned.m16n8k16.row.col.f32.f16.f16.f32 "         \
        "{%0,%1,%2,%3}, {%4,%5,%6,%7}, {%8,%9}, {%0,%1,%2,%3};"               \
        : "+f"(d##BK[4]), "+f"(d##BK[5]), "+f"(d##BK[6]), "+f"(d##BK[7])      \
        : "r"(A0), "r"(A1), "r"(A2), "r"(A3), "r"((CB).z), "r"((CB).w));      \
} while (0)

__global__ __launch_bounds__(256, 3)
void kan_kernel(float* __restrict__ out) {
    extern __shared__ char smem[];
    const int tid = threadIdx.x;
    const int bid = blockIdx.x;

    // B tile -> smem (fragment order, validated layout); 3904 uint4 total
    for (int i = tid; i < B_U4; i += 256)
        ((uint4*)smem)[i] = ((const uint4*)g_Bf)[i];
    __syncthreads();

    const int wid = tid >> 5, lane = tid & 31;
    const int g8 = lane >> 2, t4 = lane & 3;
    const int z0 = bid >> 3, y0 = (bid & 7) * 4;
    const int yl = wid >> 1, xs = (wid & 1) * 16;
    const int pos0 = z0 * 1024 + (y0 + yl) * 32 + xs;   // == bid*128 + wid*16

    const char* baseA = (const char*)g_basis +
        (uint32_t)((z0 * 1156 + (y0 + yl) * 34 + xs) * 16) + lane * 4;
    const char* baseS = (const char*)g_sil2 + (size_t)pos0 * 4 +
        (size_t)t4 * PSZ + g8 * 4;
    const char* bp = smem + lane * 16;

    float dE[8], dO[8];
    #pragma unroll
    for (int i = 0; i < 8; i++) { dE[i] = 0.0f; dO[i] = 0.0f; }

    // ---- spline chunks: fully unrolled, constant offsets, no barriers ----
    #pragma unroll
    for (int kc = 0; kc < 108; kc++) {
        const uint32_t oA = offB(2 * kc);
        const uint32_t oB = offB(2 * kc + 1);
        uint32_t a0 = *(const uint32_t*)(baseA + oA);
        uint32_t a1 = *(const uint32_t*)(baseA + oA + 128);
        uint32_t a2 = *(const uint32_t*)(baseA + oB);
        uint32_t a3 = *(const uint32_t*)(baseA + oB + 128);
        uint4 cb = *(const uint4*)(bp + kc * 512);
        if (kc & 1) { MMA2(a0, a1, a2, a3, cb, O); }
        else        { MMA2(a0, a1, a2, a3, cb, E); }
    }
    // ---- silu chunks ----
    #pragma unroll
    for (int g = 0; g < 14; g++) {
        const char* sp = baseS + (size_t)(8 * g) * PSZ;
        uint32_t a0 = *(const uint32_t*)(sp);
        uint32_t a1 = *(const uint32_t*)(sp + 32);
        uint32_t a2 = *(const uint32_t*)(sp + 4 * (size_t)PSZ);
        uint32_t a3 = *(const uint32_t*)(sp + 4 * (size_t)PSZ + 32);
        uint4 cb = *(const uint4*)(bp + (108 + g) * 512);
        if (g & 1) { MMA2(a0, a1, a2, a3, cb, O); }
        else       { MMA2(a0, a1, a2, a3, cb, E); }
    }

    // ---- epilogue ----
    const int pr0 = pos0 + g8, pr1 = pr0 + 8;
    out[(2 * t4 + 0) * OSTRIDE + pr0] = dE[0] + dO[0];
    out[(2 * t4 + 1) * OSTRIDE + pr0] = dE[1] + dO[1];
    out[(2 * t4 + 0) * OSTRIDE + pr1] = dE[2] + dO[2];
    out[(2 * t4 + 1) * OSTRIDE + pr1] = dE[3] + dO[3];
    out[(2 * t4 + 8) * OSTRIDE + pr0] = dE[4] + dO[4];
    out[(2 * t4 + 9) * OSTRIDE + pr0] = dE[5] + dO[5];
    out[(2 * t4 + 8) * OSTRIDE + pr1] = dE[6] + dO[6];
    out[(2 * t4 + 9) * OSTRIDE + pr1] = dE[7] + dO[7];
}

extern "C" void kernel_launch(void* const* d_in, const int* in_sizes, int n_in,
                              void* d_out, int out_size) {
    const float* x  = (const float*)d_in[0];
    const float* bw = (const float*)d_in[1];
    const float* sw = (const float*)d_in[2];
    const float* sc = (const float*)d_in[3];

    prep_all<<<(PREP_TOTAL + 255) / 256, 256>>>(x, bw, sw, sc);

    cudaFuncSetAttribute(kan_kernel, cudaFuncAttributeMaxDynamicSharedMemorySize,
                         B_BYTES);
    kan_kernel<<<256, 256, B_BYTES>>>((float*)d_out);
}

// round 13
// speedup vs baseline: 2.9481x; 1.3778x over previous
#include <cuda_runtime.h>
#include <cuda_fp16.h>
#include <cstdint>

// ---------------------------------------------------------------------------
// effConvKAN3D as f16 HMMA GEMM, A fragments straight from global precomputed
// arrays. K chunks: 0..107 spline (k0..7 = basis of f=2kc, k8..15 = f=2kc+1),
// 108..121 silu (col = f-16g). K split across warp halves (grid 512).
// g_basis : packed 8-half basis row per padded position (halo = basis(0))
// g_silv  : silu per padded position (half)
// ---------------------------------------------------------------------------

#define NF      216
#define OSTRIDE 32768
#define NCH     122

#define B_BYTES (NCH * 512)         // 62464
#define B_U4    (B_BYTES / 16)      // 3904
#define TBL_OFF B_BYTES             // 224 x u32 offsets
#define SCR_OFF (TBL_OFF + 1024)    // 4096B partial-accumulator scratch
#define SMEM_TOTAL (SCR_OFF + 4096) // 67584

#define NT_ITEMS   224
#define NB_ITEMS   (NCH * 128)            // 15616
#define NBAS_ITEMS (8 * 34 * 34 * 34)     // 314432
#define PREP_TOTAL (NT_ITEMS + NB_ITEMS + 2 * NBAS_ITEMS)

__device__ __align__(16) uint4    g_basis[NBAS_ITEMS];
__device__ __align__(16) __half   g_silv[NBAS_ITEMS];
__device__ __align__(16) uint32_t g_Bf[NB_ITEMS];
__device__ __align__(16) uint32_t g_offT[NT_ITEMS];

__device__ __forceinline__ uint4 basis_row(float v) {
    float tt = fmaf(v, 2.5f, 5.5f);
    float jf = floorf(tt);
    float u = tt - jf;
    int j = (int)jf;
    float u2 = u * u, u3 = u2 * u, om = 1.0f - u;
    float b0 = om * om * om * (1.0f / 6.0f);
    float b1 = fmaf(3.0f, u3, fmaf(-6.0f, u2, 4.0f)) * (1.0f / 6.0f);
    float b2 = fmaf(-3.0f, u3, fmaf(3.0f, u2, fmaf(3.0f, u, 1.0f))) * (1.0f / 6.0f);
    float b3 = u3 * (1.0f / 6.0f);
    __half2 hlo = __floats2half2_rn(b0, b1);
    __half2 hhi = __floats2half2_rn(b2, b3);
    uint32_t lo = *(uint32_t*)&hlo, hi = *(uint32_t*)&hhi;
    if ((unsigned)j > 10u) { lo = 0u; hi = 0u; j = 3; }
    uint64_t B64 = (uint64_t)lo | ((uint64_t)hi << 32);
    int t16 = j - 3;
    uint32_t wv[4];
    #pragma unroll
    for (int i = 0; i < 4; i++) {
        int d = 2 * i - t16;
        int shc = ((unsigned)d <= 3u) ? d : 0;
        uint32_t a = (uint32_t)(B64 >> (shc * 16));
        wv[i] = ((unsigned)d <= 3u) ? a : ((d == -1) ? (lo << 16) : 0u);
    }
    return make_uint4(wv[0], wv[1], wv[2], wv[3]);
}

__device__ __forceinline__ float bval(int o, int k,
                                      const float* __restrict__ bw,
                                      const float* __restrict__ sw,
                                      const float* __restrict__ sc) {
    int kc = k >> 4, col = k & 15;
    if (kc < 108) {
        int f = 2 * kc + (col >> 3), c = col & 7;
        return sw[(o * NF + f) * 8 + c] * sc[o * NF + f];
    }
    int f = 16 * (kc - 108) + col;
    return (f < NF) ? bw[o * NF + f] : 0.0f;
}

__device__ __forceinline__ float padval(const float* __restrict__ x, int t) {
    int c  = t / 39304;
    int r1 = t - c * 39304;
    int iz = r1 / 1156;
    int r2 = r1 - iz * 1156;
    int iy = r2 / 34;
    int ix = r2 - iy * 34;
    int az = iz - 1, ay = iy - 1, ax = ix - 1;
    if (((unsigned)az < 32u) & ((unsigned)ay < 32u) & ((unsigned)ax < 32u))
        return x[((c * 32 + az) * 32 + ay) * 32 + ax];
    return 0.0f;          // reference zero-pads x
}

__global__ void prep_all(const float* __restrict__ x,
                         const float* __restrict__ bw,
                         const float* __restrict__ sw,
                         const float* __restrict__ sc) {
    int t = blockIdx.x * 256 + threadIdx.x;
    if (t < NT_ITEMS) {                       // feature -> padded-volume offset
        uint32_t off = 0;
        if (t < NF) {
            int c = t / 27, r = t - c * 27;
            int dz = r / 9,  r2 = r - dz * 9;
            int dy = r2 / 3, dx = r2 - dy * 3;
            off = (uint32_t)(c * 39304 + dz * 1156 + dy * 34 + dx);
        }
        g_offT[t] = off;
        return;
    }
    t -= NT_ITEMS;
    if (t < NB_ITEMS) {                       // B fragments
        int wd = t & 3, lane = (t >> 2) & 31, kc = t >> 7;
        int g8 = lane >> 2, t4 = lane & 3;
        int o = g8 + ((wd >> 1) << 3);
        int kb = kc * 16 + ((wd & 1) << 3) + 2 * t4;
        __half2 h = __floats2half2_rn(bval(o, kb, bw, sw, sc),
                                      bval(o, kb + 1, bw, sw, sc));
        g_Bf[t] = *(uint32_t*)&h;
        return;
    }
    t -= NB_ITEMS;
    if (t < NBAS_ITEMS) {                     // basis rows
        g_basis[t] = basis_row(padval(x, t));
        return;
    }
    t -= NBAS_ITEMS;
    if (t < NBAS_ITEMS) {                     // silu volume
        float v = padval(x, t);
        g_silv[t] = __float2half_rn(__fdividef(v, 1.0f + __expf(-v)));
    }
}

// compile-time basis-array byte offset for feature f
__device__ __forceinline__ uint32_t offB(int f) {
    int c = f / 27, r = f - c * 27;
    int dz = r / 9,  r2 = r - dz * 9;
    int dy = r2 / 3, dx = r2 - dy * 3;
    return (uint32_t)((c * 39304 + dz * 1156 + dy * 34 + dx) * 16);
}

#define MMA2(A0, A1, A2, A3, CB, BK) do {                                     \
    asm volatile("mma.sync.aligned.m16n8k16.row.col.f32.f16.f16.f32 "         \
        "{%0,%1,%2,%3}, {%4,%5,%6,%7}, {%8,%9}, {%0,%1,%2,%3};"               \
        : "+f"(d##BK[0]), "+f"(d##BK[1]), "+f"(d##BK[2]), "+f"(d##BK[3])      \
        : "r"(A0), "r"(A1), "r"(A2), "r"(A3), "r"((CB).x), "r"((CB).y));      \
    asm volatile("mma.sync.aligned.m16n8k16.row.col.f32.f16.f16.f32 "         \
        "{%0,%1,%2,%3}, {%4,%5,%6,%7}, {%8,%9}, {%0,%1,%2,%3};"               \
        : "+f"(d##BK[4]), "+f"(d##BK[5]), "+f"(d##BK[6]), "+f"(d##BK[7])      \
        : "r"(A0), "r"(A1), "r"(A2), "r"(A3), "r"((CB).z), "r"((CB).w));      \
} while (0)

#define SPLINE_CHUNK(KC, BK) do {                                             \
    const uint32_t oA_ = offB(2 * (KC));                                      \
    const uint32_t oB_ = offB(2 * (KC) + 1);                                  \
    uint32_t a0_ = *(const uint32_t*)(baseA + oA_);                           \
    uint32_t a1_ = *(const uint32_t*)(baseA + oA_ + 128);                     \
    uint32_t a2_ = *(const uint32_t*)(baseA + oB_);                           \
    uint32_t a3_ = *(const uint32_t*)(baseA + oB_ + 128);                     \
    uint4 cb_ = *(const uint4*)(bp + (KC) * 512);                             \
    MMA2(a0_, a1_, a2_, a3_, cb_, BK);                                        \
} while (0)

__global__ __launch_bounds__(256, 3)
void kan_kernel(float* __restrict__ out) {
    extern __shared__ char smem[];
    const int tid = threadIdx.x;
    const int bid = blockIdx.x;

    for (int i = tid; i < B_U4; i += 256)
        ((uint4*)smem)[i] = ((const uint4*)g_Bf)[i];
    if (tid < NT_ITEMS)
        ((uint32_t*)(smem + TBL_OFF))[tid] = g_offT[tid];
    __syncthreads();

    const int wid = tid >> 5, lane = tid & 31;
    const int g8 = lane >> 2, t4 = lane & 3;
    const int wt = wid & 3, kh = wid >> 2;
    const int z0 = bid >> 4, y0 = (bid & 15) * 2;
    const int yl = wt >> 1, xs = (wt & 1) * 16;
    const int pos0 = z0 * 1024 + (y0 + yl) * 32 + xs;
    const int rowIdx = z0 * 1156 + (y0 + yl) * 34 + xs;

    const char* baseA = (const char*)g_basis + (uint32_t)(rowIdx * 16) + lane * 4;
    const unsigned short* svRow = (const unsigned short*)g_silv + rowIdx;
    const char* bp = smem + lane * 16;
    const uint32_t* offT = (const uint32_t*)(smem + TBL_OFF);

    float dE[8], dO[8];
    #pragma unroll
    for (int i = 0; i < 8; i++) { dE[i] = 0.0f; dO[i] = 0.0f; }

    if (kh == 0) {
        #pragma unroll
        for (int kc = 0; kc < 61; kc++) {
            if (kc & 1) { SPLINE_CHUNK(kc, O); } else { SPLINE_CHUNK(kc, E); }
        }
    } else {
        #pragma unroll
        for (int kc = 61; kc < 108; kc++) {
            if (kc & 1) { SPLINE_CHUNK(kc, O); } else { SPLINE_CHUNK(kc, E); }
        }
        #pragma unroll
        for (int g = 0; g < 14; g++) {
            uint2 p01 = *(const uint2*)&offT[16 * g + 2 * t4];
            uint2 p23 = *(const uint2*)&offT[16 * g + 8 + 2 * t4];
            uint32_t u00 = svRow[g8 + p01.x],     u01 = svRow[g8 + p01.y];
            uint32_t u10 = svRow[g8 + 8 + p01.x], u11 = svRow[g8 + 8 + p01.y];
            uint32_t u20 = svRow[g8 + p23.x],     u21 = svRow[g8 + p23.y];
            uint32_t u30 = svRow[g8 + 8 + p23.x], u31 = svRow[g8 + 8 + p23.y];
            uint32_t a0 = u00 | (u01 << 16);
            uint32_t a1 = u10 | (u11 << 16);
            uint32_t a2 = u20 | (u21 << 16);
            uint32_t a3 = u30 | (u31 << 16);
            uint4 cb = *(const uint4*)(bp + (108 + g) * 512);
            if (g & 1) { MMA2(a0, a1, a2, a3, cb, O); }
            else       { MMA2(a0, a1, a2, a3, cb, E); }
        }
    }

    // combine K halves through smem scratch
    float r8[8];
    #pragma unroll
    for (int i = 0; i < 8; i++) r8[i] = dE[i] + dO[i];
    float* scr = (float*)(smem + SCR_OFF) + wt * 256 + lane * 8;
    if (kh == 1) {
        *(float4*)(scr)     = make_float4(r8[0], r8[1], r8[2], r8[3]);
        *(float4*)(scr + 4) = make_float4(r8[4], r8[5], r8[6], r8[7]);
    }
    __syncthreads();
    if (kh == 0) {
        float4 p0 = *(const float4*)(scr);
        float4 p1 = *(const float4*)(scr + 4);
        const int pr0 = pos0 + g8, pr1 = pr0 + 8;
        out[(2 * t4 + 0) * OSTRIDE + pr0] = r8[0] + p0.x;
        out[(2 * t4 + 1) * OSTRIDE + pr0] = r8[1] + p0.y;
        out[(2 * t4 + 0) * OSTRIDE + pr1] = r8[2] + p0.z;
        out[(2 * t4 + 1) * OSTRIDE + pr1] = r8[3] + p0.w;
        out[(2 * t4 + 8) * OSTRIDE + pr0] = r8[4] + p1.x;
        out[(2 * t4 + 9) * OSTRIDE + pr0] = r8[5] + p1.y;
        out[(2 * t4 + 8) * OSTRIDE + pr1] = r8[6] + p1.z;
        out[(2 * t4 + 9) * OSTRIDE + pr1] = r8[7] + p1.w;
    }
}

extern "C" void kernel_launch(void* const* d_in, const int* in_sizes, int n_in,
                              void* d_out, int out_size) {
    const float* x  = (const float*)d_in[0];
    const float* bw = (const float*)d_in[1];
    const float* sw = (const float*)d_in[2];
    const float* sc = (const float*)d_in[3];

    prep_all<<<(PREP_TOTAL + 255) / 256, 256>>>(x, bw, sw, sc);

    cudaFuncSetAttribute(kan_kernel, cudaFuncAttributeMaxDynamicSharedMemorySize,
                         SMEM_TOTAL);
    kan_kernel<<<512, 256, SMEM_TOTAL>>>((float*)d_out);
}

// round 14
// speedup vs baseline: 2.9904x; 1.0144x over previous
#include <cuda_runtime.h>
#include <cuda_fp16.h>
#include <cstdint>

// ---------------------------------------------------------------------------
// effConvKAN3D as f16 HMMA GEMM, A fragments straight from global precomputed
// arrays. K chunks: 0..107 spline (k0..7 = basis of f=2kc, k8..15 = f=2kc+1),
// 108..121 silu. K split ACROSS CTAs (atomicAdd combine): kh=0 -> chunks
// 0..60, kh=1 -> 61..121; each CTA holds only its half of B in smem (31KB),
// unlocking 4 CTAs/SM.
// ---------------------------------------------------------------------------

#define NF      216
#define OSTRIDE 32768
#define NCH     122
#define HCH     61                  // chunks per K-half

#define BH_BYTES (HCH * 512)        // 31232 per-half B tile
#define BH_U4    (BH_BYTES / 16)    // 1952
#define TBL_OFF  BH_BYTES
#define SMEM_TOTAL (TBL_OFF + 1024) // 32256

#define NT_ITEMS   224
#define NB_ITEMS   (NCH * 128)            // 15616
#define NBAS_ITEMS (8 * 34 * 34 * 34)     // 314432
#define PREP_TOTAL (NT_ITEMS + NB_ITEMS + 2 * NBAS_ITEMS)

__device__ __align__(16) uint4    g_basis[NBAS_ITEMS];
__device__ __align__(16) __half   g_silv[NBAS_ITEMS];
__device__ __align__(16) uint32_t g_Bf[NB_ITEMS];
__device__ __align__(16) uint32_t g_offT[NT_ITEMS];

__device__ __forceinline__ uint4 basis_row(float v) {
    float tt = fmaf(v, 2.5f, 5.5f);
    float jf = floorf(tt);
    float u = tt - jf;
    int j = (int)jf;
    float u2 = u * u, u3 = u2 * u, om = 1.0f - u;
    float b0 = om * om * om * (1.0f / 6.0f);
    float b1 = fmaf(3.0f, u3, fmaf(-6.0f, u2, 4.0f)) * (1.0f / 6.0f);
    float b2 = fmaf(-3.0f, u3, fmaf(3.0f, u2, fmaf(3.0f, u, 1.0f))) * (1.0f / 6.0f);
    float b3 = u3 * (1.0f / 6.0f);
    __half2 hlo = __floats2half2_rn(b0, b1);
    __half2 hhi = __floats2half2_rn(b2, b3);
    uint32_t lo = *(uint32_t*)&hlo, hi = *(uint32_t*)&hhi;
    if ((unsigned)j > 10u) { lo = 0u; hi = 0u; j = 3; }
    uint64_t B64 = (uint64_t)lo | ((uint64_t)hi << 32);
    int t16 = j - 3;
    uint32_t wv[4];
    #pragma unroll
    for (int i = 0; i < 4; i++) {
        int d = 2 * i - t16;
        int shc = ((unsigned)d <= 3u) ? d : 0;
        uint32_t a = (uint32_t)(B64 >> (shc * 16));
        wv[i] = ((unsigned)d <= 3u) ? a : ((d == -1) ? (lo << 16) : 0u);
    }
    return make_uint4(wv[0], wv[1], wv[2], wv[3]);
}

__device__ __forceinline__ float bval(int o, int k,
                                      const float* __restrict__ bw,
                                      const float* __restrict__ sw,
                                      const float* __restrict__ sc) {
    int kc = k >> 4, col = k & 15;
    if (kc < 108) {
        int f = 2 * kc + (col >> 3), c = col & 7;
        return sw[(o * NF + f) * 8 + c] * sc[o * NF + f];
    }
    int f = 16 * (kc - 108) + col;
    return (f < NF) ? bw[o * NF + f] : 0.0f;
}

__device__ __forceinline__ float padval(const float* __restrict__ x, int t) {
    int c  = t / 39304;
    int r1 = t - c * 39304;
    int iz = r1 / 1156;
    int r2 = r1 - iz * 1156;
    int iy = r2 / 34;
    int ix = r2 - iy * 34;
    int az = iz - 1, ay = iy - 1, ax = ix - 1;
    if (((unsigned)az < 32u) & ((unsigned)ay < 32u) & ((unsigned)ax < 32u))
        return x[((c * 32 + az) * 32 + ay) * 32 + ax];
    return 0.0f;          // reference zero-pads x
}

__global__ void prep_all(const float* __restrict__ x,
                         const float* __restrict__ bw,
                         const float* __restrict__ sw,
                         const float* __restrict__ sc) {
    int t = blockIdx.x * 256 + threadIdx.x;
    if (t < NT_ITEMS) {                       // feature -> padded-volume offset
        uint32_t off = 0;
        if (t < NF) {
            int c = t / 27, r = t - c * 27;
            int dz = r / 9,  r2 = r - dz * 9;
            int dy = r2 / 3, dx = r2 - dy * 3;
            off = (uint32_t)(c * 39304 + dz * 1156 + dy * 34 + dx);
        }
        g_offT[t] = off;
        return;
    }
    t -= NT_ITEMS;
    if (t < NB_ITEMS) {                       // B fragments
        int wd = t & 3, lane = (t >> 2) & 31, kc = t >> 7;
        int g8 = lane >> 2, t4 = lane & 3;
        int o = g8 + ((wd >> 1) << 3);
        int kb = kc * 16 + ((wd & 1) << 3) + 2 * t4;
        __half2 h = __floats2half2_rn(bval(o, kb, bw, sw, sc),
                                      bval(o, kb + 1, bw, sw, sc));
        g_Bf[t] = *(uint32_t*)&h;
        return;
    }
    t -= NB_ITEMS;
    if (t < NBAS_ITEMS) {                     // basis rows
        g_basis[t] = basis_row(padval(x, t));
        return;
    }
    t -= NBAS_ITEMS;
    if (t < NBAS_ITEMS) {                     // silu volume
        float v = padval(x, t);
        g_silv[t] = __float2half_rn(__fdividef(v, 1.0f + __expf(-v)));
    }
}

// compile-time basis-array byte offset for feature f
__device__ __forceinline__ uint32_t offB(int f) {
    int c = f / 27, r = f - c * 27;
    int dz = r / 9,  r2 = r - dz * 9;
    int dy = r2 / 3, dx = r2 - dy * 3;
    return (uint32_t)((c * 39304 + dz * 1156 + dy * 34 + dx) * 16);
}

#define MMA2(A0, A1, A2, A3, CB) do {                                         \
    asm volatile("mma.sync.aligned.m16n8k16.row.col.f32.f16.f16.f32 "         \
        "{%0,%1,%2,%3}, {%4,%5,%6,%7}, {%8,%9}, {%0,%1,%2,%3};"               \
        : "+f"(d[0]), "+f"(d[1]), "+f"(d[2]), "+f"(d[3])                      \
        : "r"(A0), "r"(A1), "r"(A2), "r"(A3), "r"((CB).x), "r"((CB).y));      \
    asm volatile("mma.sync.aligned.m16n8k16.row.col.f32.f16.f16.f32 "         \
        "{%0,%1,%2,%3}, {%4,%5,%6,%7}, {%8,%9}, {%0,%1,%2,%3};"               \
        : "+f"(d[4]), "+f"(d[5]), "+f"(d[6]), "+f"(d[7])                      \
        : "r"(A0), "r"(A1), "r"(A2), "r"(A3), "r"((CB).z), "r"((CB).w));      \
} while (0)

#define SPLINE_CHUNK(KC, LC) do {                                             \
    const uint32_t oA_ = offB(2 * (KC));                                      \
    const uint32_t oB_ = offB(2 * (KC) + 1);                                  \
    uint32_t a0_ = *(const uint32_t*)(baseA + oA_);                           \
    uint32_t a1_ = *(const uint32_t*)(baseA + oA_ + 128);                     \
    uint32_t a2_ = *(const uint32_t*)(baseA + oB_);                           \
    uint32_t a3_ = *(const uint32_t*)(baseA + oB_ + 128);                     \
    uint4 cb_ = *(const uint4*)(bp + (LC) * 512);                             \
    MMA2(a0_, a1_, a2_, a3_, cb_);                                            \
} while (0)

__global__ __launch_bounds__(256, 4)
void kan_kernel(float* __restrict__ out) {
    extern __shared__ char smem[];
    const int tid = threadIdx.x;
    const int bid = blockIdx.x;
    const int kh = bid & 1;          // K half
    const int pb = bid >> 1;         // position block (0..255, 128 pos each)

    // copy this half's B fragments (+ offset table)
    {
        const uint4* src = (const uint4*)(g_Bf + (kh ? HCH * 128 : 0));
        for (int i = tid; i < BH_U4; i += 256)
            ((uint4*)smem)[i] = src[i];
        if (tid < NT_ITEMS)
            ((uint32_t*)(smem + TBL_OFF))[tid] = g_offT[tid];
    }
    __syncthreads();

    const int wid = tid >> 5, lane = tid & 31;
    const int g8 = lane >> 2, t4 = lane & 3;
    const int z0 = pb >> 3, y0 = (pb & 7) * 4;
    const int yl = wid >> 1, xs = (wid & 1) * 16;
    const int pos0 = z0 * 1024 + (y0 + yl) * 32 + xs;
    const int rowIdx = z0 * 1156 + (y0 + yl) * 34 + xs;

    const char* baseA = (const char*)g_basis + (uint32_t)(rowIdx * 16) + lane * 4;
    const unsigned short* svRow = (const unsigned short*)g_silv + rowIdx;
    const char* bp = smem + lane * 16;
    const uint32_t* offT = (const uint32_t*)(smem + TBL_OFF);

    float d[8];
    #pragma unroll
    for (int i = 0; i < 8; i++) d[i] = 0.0f;

    if (kh == 0) {
        #pragma unroll
        for (int kc = 0; kc < 61; kc++) SPLINE_CHUNK(kc, kc);
    } else {
        #pragma unroll
        for (int kc = 61; kc < 108; kc++) SPLINE_CHUNK(kc, kc - 61);
        #pragma unroll
        for (int g = 0; g < 14; g++) {
            uint2 p01 = *(const uint2*)&offT[16 * g + 2 * t4];
            uint2 p23 = *(const uint2*)&offT[16 * g + 8 + 2 * t4];
            uint32_t u00 = svRow[g8 + p01.x],     u01 = svRow[g8 + p01.y];
            uint32_t u10 = svRow[g8 + 8 + p01.x], u11 = svRow[g8 + 8 + p01.y];
            uint32_t u20 = svRow[g8 + p23.x],     u21 = svRow[g8 + p23.y];
            uint32_t u30 = svRow[g8 + 8 + p23.x], u31 = svRow[g8 + 8 + p23.y];
            uint32_t a0 = u00 | (u01 << 16);
            uint32_t a1 = u10 | (u11 << 16);
            uint32_t a2 = u20 | (u21 << 16);
            uint32_t a3 = u30 | (u31 << 16);
            uint4 cb = *(const uint4*)(bp + (47 + g) * 512);
            MMA2(a0, a1, a2, a3, cb);
        }
    }

    // combine K halves via atomics into zeroed output
    const int pr0 = pos0 + g8, pr1 = pr0 + 8;
    atomicAdd(&out[(2 * t4 + 0) * OSTRIDE + pr0], d[0]);
    atomicAdd(&out[(2 * t4 + 1) * OSTRIDE + pr0], d[1]);
    atomicAdd(&out[(2 * t4 + 0) * OSTRIDE + pr1], d[2]);
    atomicAdd(&out[(2 * t4 + 1) * OSTRIDE + pr1], d[3]);
    atomicAdd(&out[(2 * t4 + 8) * OSTRIDE + pr0], d[4]);
    atomicAdd(&out[(2 * t4 + 9) * OSTRIDE + pr0], d[5]);
    atomicAdd(&out[(2 * t4 + 8) * OSTRIDE + pr1], d[6]);
    atomicAdd(&out[(2 * t4 + 9) * OSTRIDE + pr1], d[7]);
}

extern "C" void kernel_launch(void* const* d_in, const int* in_sizes, int n_in,
                              void* d_out, int out_size) {
    const float* x  = (const float*)d_in[0];
    const float* bw = (const float*)d_in[1];
    const float* sw = (const float*)d_in[2];
    const float* sc = (const float*)d_in[3];

    cudaMemsetAsync(d_out, 0, (size_t)out_size * sizeof(float));
    prep_all<<<(PREP_TOTAL + 255) / 256, 256>>>(x, bw, sw, sc);

    cudaFuncSetAttribute(kan_kernel, cudaFuncAttributeMaxDynamicSharedMemorySize,
                         SMEM_TOTAL);
    kan_kernel<<<512, 256, SMEM_TOTAL>>>((float*)d_out);
}